// round 13
// baseline (speedup 1.0000x reference)
#include <cuda_runtime.h>
#include <cuda_bf16.h>
#include <cstdint>
#include <float.h>

#define BB    8
#define NN    2048
#define KK    16
#define CIN   64
#define COUT  128
#define BN_EPS 1e-3f
#define LARGE_DIST 1e9f
#define MARGIN 2e-4f

#define SPLIT 8
#define CAND  (NN / SPLIT)   // 256
#define NPTS  (BB * NN)      // 16384

// ---- global scratch -------------------------------------------------------
__device__ float          g_pd[NPTS * SPLIT * KK];
__device__ int            g_pi[NPTS * SPLIT * KK];
__device__ int            g_idx[NPTS * KK];
__device__ unsigned short g_h_hi[(size_t)NPTS * 512];
__device__ unsigned short g_h_lo[(size_t)NPTS * 512];
__device__ float          g_X[(size_t)NPTS * 256];
__device__ unsigned short g_t_hi[(size_t)NPTS * 1024];
__device__ unsigned short g_t_lo[(size_t)NPTS * 1024];
__device__ unsigned short g_w2t_hi[256 * 512];
__device__ unsigned short g_w2t_lo[256 * 512];
__device__ unsigned short g_wft_hi[128 * 1024];
__device__ unsigned short g_wft_lo[128 * 1024];

// ---- packed fp32x2 helpers ------------------------------------------------
__device__ __forceinline__ unsigned long long pack2(float lo, float hi) {
    unsigned long long r;
    asm("mov.b64 %0, {%1, %2};" : "=l"(r) : "f"(lo), "f"(hi));
    return r;
}
__device__ __forceinline__ float2 unpack2(unsigned long long v) {
    float2 r;
    asm("mov.b64 {%0, %1}, %2;" : "=f"(r.x), "=f"(r.y) : "l"(v));
    return r;
}
__device__ __forceinline__ void ffma2(unsigned long long& a,
                                      unsigned long long x,
                                      unsigned long long y) {
    asm("fma.rn.f32x2 %0, %1, %2, %0;" : "+l"(a) : "l"(x), "l"(y));
}

// ---- mma.sync helpers ------------------------------------------------------
__device__ __forceinline__ uint32_t smem_u32(const void* p) {
    uint32_t a;
    asm("{ .reg .u64 t; cvta.to.shared.u64 t, %1; cvt.u32.u64 %0, t; }"
        : "=r"(a) : "l"(p));
    return a;
}
__device__ __forceinline__ void ldm_x4(uint32_t* r, uint32_t addr) {
    asm volatile("ldmatrix.sync.aligned.m8n8.x4.shared.b16 {%0,%1,%2,%3}, [%4];"
                 : "=r"(r[0]), "=r"(r[1]), "=r"(r[2]), "=r"(r[3]) : "r"(addr));
}
__device__ __forceinline__ void ldm_x2(uint32_t* r, uint32_t addr) {
    asm volatile("ldmatrix.sync.aligned.m8n8.x2.shared.b16 {%0,%1}, [%2];"
                 : "=r"(r[0]), "=r"(r[1]) : "r"(addr));
}
__device__ __forceinline__ void mma_bf16(float* d, const uint32_t* a,
                                         const uint32_t* b) {
    asm volatile(
        "mma.sync.aligned.m16n8k16.row.col.f32.bf16.bf16.f32 "
        "{%0,%1,%2,%3}, {%4,%5,%6,%7}, {%8,%9}, {%0,%1,%2,%3};"
        : "+f"(d[0]), "+f"(d[1]), "+f"(d[2]), "+f"(d[3])
        : "r"(a[0]), "r"(a[1]), "r"(a[2]), "r"(a[3]), "r"(b[0]), "r"(b[1]));
}

// ---------------------------------------------------------------------------
// KNN
// ---------------------------------------------------------------------------
__device__ __forceinline__ void insert16(float* bd, int* bi, float d, int j) {
    bd[KK - 1] = d; bi[KK - 1] = j;
#pragma unroll
    for (int t = KK - 1; t > 0; --t) {
        if (bd[t] < bd[t - 1]) {
            float td = bd[t]; bd[t] = bd[t - 1]; bd[t - 1] = td;
            int   ti = bi[t]; bi[t] = bi[t - 1]; bi[t - 1] = ti;
        }
    }
}

// prune-scan KNN (R10-winning body): hot path uses approx dist (norm trick,
// f32x2); on pack hit, recompute EXACT reference distances for all 4.
__global__ __launch_bounds__(128)
void knn_part(const float* __restrict__ xyz,
              float* __restrict__ pd, int* __restrict__ pi) {
    __shared__ __align__(16) float s_x[NN], s_y[NN], s_z[NN], s_pn[NN], s_pen[NN];
    const int tid = threadIdx.x;
    const int qg  = blockIdx.x >> 3;
    const int sp  = blockIdx.x & 7;
    const int g   = qg * 128 + tid;
    const int b   = g >> 11;
    const int n   = g & (NN - 1);

    for (int j = tid; j < NN; j += 128) {
        const float* p = xyz + ((size_t)b * NN + j) * 3;
        float x = p[0], y = p[1], z = p[2];
        float pen = (x != 0.0f || y != 0.0f || z != 0.0f) ? 0.0f : LARGE_DIST;
        s_x[j] = x; s_y[j] = y; s_z[j] = z;
        s_pen[j] = pen;
        s_pn[j]  = x * x + y * y + z * z + pen;
    }
    __syncthreads();

    const float* qp = xyz + ((size_t)b * NN + n) * 3;
    const float qx = qp[0], qy = qp[1], qz = qp[2];
    const float qnorm = qx * qx + qy * qy + qz * qz;
    const unsigned long long mx2 = pack2(-2.0f * qx, -2.0f * qx);
    const unsigned long long my2 = pack2(-2.0f * qy, -2.0f * qy);
    const unsigned long long mz2 = pack2(-2.0f * qz, -2.0f * qz);

    float bd[KK]; int bi[KK];
#pragma unroll
    for (int t = 0; t < KK; t++) { bd[t] = FLT_MAX; bi[t] = 0; }
    float boundp = FLT_MAX;

    const int j0 = sp * CAND;
#pragma unroll 4
    for (int jj = 0; jj < CAND; jj += 4) {
        const int j = j0 + jj;
        ulonglong2 Xv = *(const ulonglong2*)&s_x[j];
        ulonglong2 Yv = *(const ulonglong2*)&s_y[j];
        ulonglong2 Zv = *(const ulonglong2*)&s_z[j];
        ulonglong2 Nv = *(const ulonglong2*)&s_pn[j];
        unsigned long long d0 = Nv.x, d1 = Nv.y;
        ffma2(d0, mx2, Xv.x); ffma2(d0, my2, Yv.x); ffma2(d0, mz2, Zv.x);
        ffma2(d1, mx2, Xv.y); ffma2(d1, my2, Yv.y); ffma2(d1, mz2, Zv.y);
        float2 a = unpack2(d0), c = unpack2(d1);
        float mn = fminf(fminf(a.x, a.y), fminf(c.x, c.y));
        if (mn < boundp) {
#pragma unroll
            for (int t4 = 0; t4 < 4; t4++) {
                float px = s_x[j + t4], py = s_y[j + t4], pz = s_z[j + t4];
                float dx = qx - px, dy = qy - py, dz = qz - pz;
                float d = dx * dx + dy * dy + dz * dz + s_pen[j + t4];
                if (d < bd[KK - 1]) insert16(bd, bi, d, j + t4);
            }
            boundp = bd[KK - 1] - qnorm + MARGIN;
        }
    }

    float* po = pd + ((size_t)g * SPLIT + sp) * KK;
    int*   io = pi + ((size_t)g * SPLIT + sp) * KK;
#pragma unroll
    for (int t = 0; t < KK; t++) { po[t] = bd[t]; io[t] = bi[t]; }
}

// 2-phase merge, 4 threads/query (64 queries/block): each merges 32 of the 128
// partial entries (ascending split order), part-0 folds the other 3 lists.
__global__ __launch_bounds__(256)
void knn_merge(const float* __restrict__ pd, const int* __restrict__ pi,
               int* __restrict__ idx_out) {
    __shared__ float sd[192][17];
    __shared__ int   si[192][17];
    const int tid  = threadIdx.x;
    const int q    = tid >> 2;     // local query 0..63
    const int part = tid & 3;      // 0..3
    const int g    = blockIdx.x * 64 + q;

    float bd[KK]; int bi[KK];
#pragma unroll
    for (int t = 0; t < KK; t++) { bd[t] = FLT_MAX; bi[t] = 0; }

    const float* pp = pd + (size_t)g * SPLIT * KK + part * 32;
    const int*   ii = pi + (size_t)g * SPLIT * KK + part * 32;
#pragma unroll 4
    for (int c = 0; c < 32; c++) {
        float d = pp[c];
        if (d < bd[KK - 1]) insert16(bd, bi, d, ii[c]);
    }

    if (part) {
        int row = q * 3 + (part - 1);
#pragma unroll
        for (int t = 0; t < KK; t++) { sd[row][t] = bd[t]; si[row][t] = bi[t]; }
    }
    __syncthreads();
    if (!part) {
#pragma unroll
        for (int h = 0; h < 3; h++) {
            int row = q * 3 + h;
#pragma unroll
            for (int c = 0; c < KK; c++) {
                float d = sd[row][c];
                if (d < bd[KK - 1]) insert16(bd, bi, d, si[row][c]);
            }
        }
#pragma unroll
        for (int t = 0; t < KK; t++) idx_out[(size_t)g * KK + t] = bi[t];
    }
}

// ---------------------------------------------------------------------------
// k2: h precompute -> bf16 hi/lo
// ---------------------------------------------------------------------------
__global__ __launch_bounds__(256)
void h_kernel(const float* __restrict__ xyz, const int* __restrict__ idx,
              const float* __restrict__ w1, const float* __restrict__ b1,
              const float* __restrict__ gamma1, const float* __restrict__ beta1,
              const float* __restrict__ mean1, const float* __restrict__ var1,
              unsigned short* __restrict__ Hhi, unsigned short* __restrict__ Hlo) {
    __shared__ float sw[96], sb[32], ssc[32], ssh[32];
    const int tid = threadIdx.x;
    if (tid < 96) sw[tid] = w1[tid];
    if (tid < 32) {
        sb[tid] = b1[tid];
        float sc = gamma1[tid] * rsqrtf(var1[tid] + BN_EPS);
        ssc[tid] = sc;
        ssh[tid] = beta1[tid] - mean1[tid] * sc;
    }
    __syncthreads();

    const int g0 = blockIdx.x * 16;
    const int p  = tid >> 4;
    const int k  = tid & 15;
    const int g  = g0 + p;
    const int b  = g >> 11;
    const int n  = g & (NN - 1);
    const int nbr = idx[(size_t)g * KK + k];

    const float* qp = xyz + ((size_t)b * NN + n) * 3;
    const float* np = xyz + ((size_t)b * NN + nbr) * 3;
    float qx = qp[0], qy = qp[1], qz = qp[2];
    float px = np[0], py = np[1], pz = np[2];
    float nm = (px != 0.0f || py != 0.0f || pz != 0.0f) ? 1.0f : 0.0f;
    float r0 = nm * (px - qx), r1 = nm * (py - qy), r2 = nm * (pz - qz);

    unsigned short hh[32], ll[32];
#pragma unroll
    for (int d = 0; d < 32; d++) {
        float v = r0 * sw[d] + r1 * sw[32 + d] + r2 * sw[64 + d] + sb[d];
        v = fmaxf(v, 0.0f);
        v = v * ssc[d] + ssh[d];
        __nv_bfloat16 hv = __float2bfloat16(v);
        float res = v - __bfloat162float(hv);
        hh[d] = __bfloat16_as_ushort(hv);
        ll[d] = __bfloat16_as_ushort(__float2bfloat16(res));
    }
    size_t off = (size_t)g * 512 + k * 32;
#pragma unroll
    for (int q = 0; q < 4; q++) {
        *(uint4*)(Hhi + off + q * 8) = *(uint4*)&hh[q * 8];
        *(uint4*)(Hlo + off + q * 8) = *(uint4*)&ll[q * 8];
    }
}

// ---------------------------------------------------------------------------
// prep: transpose + bf16-split a weight matrix  W[K][N] -> out[N][K]
// ---------------------------------------------------------------------------
__global__ void prep_bT(const float* __restrict__ W,
                        unsigned short* __restrict__ hi,
                        unsigned short* __restrict__ lo, int K, int N) {
    int i = blockIdx.x * 256 + threadIdx.x;
    if (i >= K * N) return;
    int n = i % N, k = i / N;
    float v = W[i];
    __nv_bfloat16 h = __float2bfloat16(v);
    float r = v - __bfloat162float(h);
    hi[(size_t)n * K + k] = __bfloat16_as_ushort(h);
    lo[(size_t)n * K + k] = __bfloat16_as_ushort(__float2bfloat16(r));
}

// ---------------------------------------------------------------------------
// mma.sync bf16 3-term GEMM
// ---------------------------------------------------------------------------
template<int BM, int NMAT, int KTOT, int EPI>
__global__ __launch_bounds__(256)
void mma_gemm(const unsigned short* __restrict__ Ahi,
              const unsigned short* __restrict__ Alo,
              const unsigned short* __restrict__ Bhi,
              const unsigned short* __restrict__ Blo,
              const float* __restrict__ e0, const float* __restrict__ e1,
              const float* __restrict__ e2, const float* __restrict__ e3,
              const float* __restrict__ xyz, float* __restrict__ C) {
    constexpr int MT = BM / 32;
    constexpr int LDS_H = 40;
    __shared__ __align__(16) unsigned short sAh[BM * LDS_H];
    __shared__ __align__(16) unsigned short sAl[BM * LDS_H];
    __shared__ __align__(16) unsigned short sBh[128 * LDS_H];
    __shared__ __align__(16) unsigned short sBl[128 * LDS_H];

    const int tid  = threadIdx.x;
    const int lane = tid & 31;
    const int wid  = tid >> 5;
    const int wr   = wid >> 2;
    const int wc   = wid & 3;
    const int g0   = blockIdx.x * BM;
    const int col0 = blockIdx.y * 128;

    const uint32_t aHiB = smem_u32(sAh), aLoB = smem_u32(sAl);
    const uint32_t bHiB = smem_u32(sBh), bLoB = smem_u32(sBl);

    float acc[MT][4][4];
#pragma unroll
    for (int m = 0; m < MT; m++)
#pragma unroll
        for (int n = 0; n < 4; n++)
#pragma unroll
            for (int q = 0; q < 4; q++) acc[m][n][q] = 0.0f;

    const int q8 = lane >> 3;
    const int r8 = lane & 7;

    for (int k0 = 0; k0 < KTOT; k0 += 32) {
#pragma unroll
        for (int v = tid; v < BM * 4; v += 256) {
            int row = v >> 2, c8 = (v & 3) * 8;
            int dst = row * LDS_H + c8;
            size_t src = (size_t)(g0 + row) * KTOT + k0 + c8;
            *(uint4*)(sAh + dst) = *(const uint4*)(Ahi + src);
            *(uint4*)(sAl + dst) = *(const uint4*)(Alo + src);
        }
#pragma unroll
        for (int v = tid; v < 512; v += 256) {
            int row = v >> 2, c8 = (v & 3) * 8;
            int dst = row * LDS_H + c8;
            size_t src = (size_t)(col0 + row) * KTOT + k0 + c8;
            *(uint4*)(sBh + dst) = *(const uint4*)(Bhi + src);
            *(uint4*)(sBl + dst) = *(const uint4*)(Blo + src);
        }
        __syncthreads();

#pragma unroll
        for (int ks = 0; ks < 2; ks++) {
            const int kk = ks * 16;
            uint32_t ah[MT][4], al[MT][4];
#pragma unroll
            for (int m = 0; m < MT; m++) {
                int arow = wr * (BM / 2) + m * 16 + (q8 & 1) * 8 + r8;
                int acol = kk + (q8 >> 1) * 8;
                uint32_t off = (uint32_t)(arow * LDS_H + acol) * 2;
                ldm_x4(ah[m], aHiB + off);
                ldm_x4(al[m], aLoB + off);
            }
            uint32_t bh[4][2], bl[4][2];
#pragma unroll
            for (int n = 0; n < 4; n++) {
                int nrow = wc * 32 + n * 8 + r8;
                int ncol = kk + (q8 & 1) * 8;
                uint32_t off = (uint32_t)(nrow * LDS_H + ncol) * 2;
                ldm_x2(bh[n], bHiB + off);
                ldm_x2(bl[n], bLoB + off);
            }
#pragma unroll
            for (int m = 0; m < MT; m++)
#pragma unroll
                for (int n = 0; n < 4; n++) {
                    mma_bf16(acc[m][n], ah[m], bh[n]);
                    mma_bf16(acc[m][n], ah[m], bl[n]);
                    mma_bf16(acc[m][n], al[m], bh[n]);
                }
        }
        __syncthreads();
    }

#pragma unroll
    for (int m = 0; m < MT; m++) {
        int r1 = g0 + wr * (BM / 2) + m * 16 + (lane >> 2);
        int r2 = r1 + 8;
        float m1 = 1.0f, m2 = 1.0f;
        if (EPI == 1) {
            const float* p1 = xyz + (size_t)r1 * 3;
            const float* p2 = xyz + (size_t)r2 * 3;
            m1 = (p1[0] != 0.0f || p1[1] != 0.0f || p1[2] != 0.0f) ? 1.0f : 0.0f;
            m2 = (p2[0] != 0.0f || p2[1] != 0.0f || p2[2] != 0.0f) ? 1.0f : 0.0f;
        }
#pragma unroll
        for (int n = 0; n < 4; n++) {
            int c = col0 + wc * 32 + n * 8 + (lane & 3) * 2;
            float v0 = acc[m][n][0], v1 = acc[m][n][1];
            float v2 = acc[m][n][2], v3 = acc[m][n][3];
            if (EPI == 0) {
                float bb0 = e0[c], bb1 = e0[c + 1];
                v0 += bb0; v1 += bb1; v2 += bb0; v3 += bb1;
            } else {
                float sc0 = e0[c] * rsqrtf(e3[c] + BN_EPS);
                float sh0 = e1[c] - e2[c] * sc0;
                float sc1 = e0[c + 1] * rsqrtf(e3[c + 1] + BN_EPS);
                float sh1 = e1[c + 1] - e2[c + 1] * sc1;
                v0 = fmaxf(v0 * sc0 + sh0, 0.0f) * m1;
                v1 = fmaxf(v1 * sc1 + sh1, 0.0f) * m1;
                v2 = fmaxf(v2 * sc0 + sh0, 0.0f) * m2;
                v3 = fmaxf(v3 * sc1 + sh1, 0.0f) * m2;
            }
            *(float2*)(C + (size_t)r1 * NMAT + c) = make_float2(v0, v1);
            *(float2*)(C + (size_t)r2 * NMAT + c) = make_float2(v2, v3);
        }
    }
}

// ---------------------------------------------------------------------------
// FUSED k4+k5: lifted (smem only) -> transformed = X @ lifted -> bf16 hi/lo.
// ---------------------------------------------------------------------------
__global__ __launch_bounds__(256)
void lift_xform(const float* __restrict__ feat, const int* __restrict__ idx,
                const float* __restrict__ xyz, const float* __restrict__ wl,
                const float* __restrict__ gamma_l, const float* __restrict__ beta_l,
                const float* __restrict__ mean_l, const float* __restrict__ var_l,
                const float* __restrict__ Xg,
                unsigned short* __restrict__ Thi,
                unsigned short* __restrict__ Tlo) {
    extern __shared__ float sm[];
    float* As    = sm;              // [64][256] featT; later sL[16*1024]
    float* Bs    = sm + 16384;      // [64][64] wl; later sX[16*256]
    float* smask = sm + 20480;      // [256]
    float* ssc   = sm + 20736;      // [64]
    float* ssh   = sm + 20800;      // [64]

    const int tid  = threadIdx.x;
    const int g0   = blockIdx.x * 16;
    const int row0 = blockIdx.x * 256;

    {
        int grow = row0 + tid;
        int nbr  = idx[grow];
        int b    = grow >> 15;
        const float* np = xyz + ((size_t)(b << 11) + nbr) * 3;
        smask[tid] = (np[0] != 0.0f || np[1] != 0.0f || np[2] != 0.0f) ? 1.0f : 0.0f;
        if (tid < 64) {
            float sc = gamma_l[tid] * rsqrtf(var_l[tid] + BN_EPS);
            ssc[tid] = sc;
            ssh[tid] = beta_l[tid] - mean_l[tid] * sc;
        }
    }
    {
        int kr = tid >> 4;
        int cc = (tid & 15) * 4;
#pragma unroll
        for (int h2 = 0; h2 < 4; h2++)
            *(float4*)&Bs[(kr + h2 * 16) * 64 + cc] =
                *(const float4*)(wl + (size_t)(kr + h2 * 16) * 64 + cc);
    }
    {
        int cc = (tid & 15) * 4;
#pragma unroll
        for (int h2 = 0; h2 < 16; h2++) {
            int r    = (tid >> 4) + h2 * 16;
            int grow = row0 + r;
            int nbr  = idx[grow];
            int b    = grow >> 15;
            float4 f = *(const float4*)(feat + ((size_t)(b << 11) + nbr) * 64 + cc);
            As[(cc + 0) * 256 + r] = f.x;
            As[(cc + 1) * 256 + r] = f.y;
            As[(cc + 2) * 256 + r] = f.z;
            As[(cc + 3) * 256 + r] = f.w;
        }
    }
    __syncthreads();

    const int tx = tid & 7;
    const int ty = tid >> 3;
    unsigned long long acc1[8][4];
#pragma unroll
    for (int i = 0; i < 8; i++)
#pragma unroll
        for (int q = 0; q < 4; q++) acc1[i][q] = 0ull;

#pragma unroll 8
    for (int kk = 0; kk < 64; kk++) {
        float a[8];
        *(float4*)&a[0] = *(const float4*)&As[kk * 256 + ty * 8];
        *(float4*)&a[4] = *(const float4*)&As[kk * 256 + ty * 8 + 4];
        ulonglong2 bA = *(const ulonglong2*)&Bs[kk * 64 + tx * 8];
        ulonglong2 bB = *(const ulonglong2*)&Bs[kk * 64 + tx * 8 + 4];
#pragma unroll
        for (int i = 0; i < 8; i++) {
            unsigned long long a2 = pack2(a[i], a[i]);
            ffma2(acc1[i][0], a2, bA.x);
            ffma2(acc1[i][1], a2, bA.y);
            ffma2(acc1[i][2], a2, bB.x);
            ffma2(acc1[i][3], a2, bB.y);
        }
    }
    __syncthreads();   // all As/Bs reads done -> overlay

#pragma unroll
    for (int i = 0; i < 8; i++) {
        int rloc = ty * 8 + i;
        float m  = smask[rloc];
        float v[8];
#pragma unroll
        for (int q = 0; q < 8; q++) {
            float2 p = unpack2(acc1[i][q >> 1]);
            int nc = tx * 8 + q;
            float x = ((q & 1) ? p.y : p.x) * ssc[nc] + ssh[nc];
            v[q] = fmaxf(x, 0.0f) * m;
        }
        float* cp = As + rloc * 64 + tx * 8;
        *(float4*)cp       = make_float4(v[0], v[1], v[2], v[3]);
        *(float4*)(cp + 4) = make_float4(v[4], v[5], v[6], v[7]);
    }
    for (int e = tid * 4; e < 4096; e += 1024)
        *(float4*)&Bs[e] = *(const float4*)(Xg + (size_t)g0 * 256 + e);
    __syncthreads();

    const int p = tid >> 4;
    const int i = tid & 15;

    float xr[16];
    {
        const float4* xp = (const float4*)&Bs[p * 256 + i * 16];
#pragma unroll
        for (int q = 0; q < 4; q++) *(float4*)&xr[q * 4] = xp[q];
    }

    unsigned long long acc[32];
#pragma unroll
    for (int q = 0; q < 32; q++) acc[q] = 0ull;

#pragma unroll
    for (int j = 0; j < 16; j++) {
        unsigned long long xv = pack2(xr[j], xr[j]);
        const ulonglong2* lp = (const ulonglong2*)&As[p * 1024 + j * 64];
#pragma unroll
        for (int q = 0; q < 16; q++) {
            ulonglong2 lv = lp[q];
            ffma2(acc[2 * q],     xv, lv.x);
            ffma2(acc[2 * q + 1], xv, lv.y);
        }
    }

    unsigned short hh[64], ll[64];
#pragma unroll
    for (int q = 0; q < 32; q++) {
        float2 a = unpack2(acc[q]);
        __nv_bfloat16 h0 = __float2bfloat16(a.x);
        __nv_bfloat16 h1 = __float2bfloat16(a.y);
        hh[2 * q]     = __bfloat16_as_ushort(h0);
        hh[2 * q + 1] = __bfloat16_as_ushort(h1);
        ll[2 * q]     = __bfloat16_as_ushort(__float2bfloat16(a.x - __bfloat162float(h0)));
        ll[2 * q + 1] = __bfloat16_as_ushort(__float2bfloat16(a.y - __bfloat162float(h1)));
    }
    size_t off = (size_t)(g0 + p) * 1024 + i * 64;
#pragma unroll
    for (int q = 0; q < 8; q++) {
        *(uint4*)(Thi + off + q * 8) = *(uint4*)&hh[q * 8];
        *(uint4*)(Tlo + off + q * 8) = *(uint4*)&ll[q * 8];
    }
}

// ---------------------------------------------------------------------------
extern "C" void kernel_launch(void* const* d_in, const int* in_sizes, int n_in,
                              void* d_out, int out_size) {
    const float* xyz     = (const float*)d_in[0];
    const float* feat    = (const float*)d_in[1];
    const float* w1      = (const float*)d_in[2];
    const float* b1      = (const float*)d_in[3];
    const float* gamma1  = (const float*)d_in[4];
    const float* beta1   = (const float*)d_in[5];
    const float* mean1   = (const float*)d_in[6];
    const float* var1    = (const float*)d_in[7];
    const float* w2      = (const float*)d_in[8];
    const float* b2      = (const float*)d_in[9];
    const float* wl      = (const float*)d_in[10];
    const float* gamma_l = (const float*)d_in[11];
    const float* beta_l  = (const float*)d_in[12];
    const float* mean_l  = (const float*)d_in[13];
    const float* var_l   = (const float*)d_in[14];
    const float* wf      = (const float*)d_in[15];
    const float* gamma_f = (const float*)d_in[16];
    const float* beta_f  = (const float*)d_in[17];
    const float* mean_f  = (const float*)d_in[18];
    const float* var_f   = (const float*)d_in[19];
    float* out = (float*)d_out;

    float *pd_ptr, *X_ptr;
    int *pi_ptr, *idx_ptr;
    unsigned short *hhi, *hlo, *thi, *tlo, *w2hi, *w2lo, *wfhi, *wflo;
    cudaGetSymbolAddress((void**)&pd_ptr, g_pd);
    cudaGetSymbolAddress((void**)&pi_ptr, g_pi);
    cudaGetSymbolAddress((void**)&idx_ptr, g_idx);
    cudaGetSymbolAddress((void**)&hhi, g_h_hi);
    cudaGetSymbolAddress((void**)&hlo, g_h_lo);
    cudaGetSymbolAddress((void**)&X_ptr, g_X);
    cudaGetSymbolAddress((void**)&thi, g_t_hi);
    cudaGetSymbolAddress((void**)&tlo, g_t_lo);
    cudaGetSymbolAddress((void**)&w2hi, g_w2t_hi);
    cudaGetSymbolAddress((void**)&w2lo, g_w2t_lo);
    cudaGetSymbolAddress((void**)&wfhi, g_wft_hi);
    cudaGetSymbolAddress((void**)&wflo, g_wft_lo);

    knn_part<<<(NPTS / 128) * SPLIT, 128>>>(xyz, pd_ptr, pi_ptr);
    prep_bT<<<(512 * 256 + 255) / 256, 256>>>(w2, w2hi, w2lo, 512, 256);
    prep_bT<<<(1024 * 128 + 255) / 256, 256>>>(wf, wfhi, wflo, 1024, 128);
    knn_merge<<<NPTS / 64, 256>>>(pd_ptr, pi_ptr, idx_ptr);

    h_kernel<<<NPTS / 16, 256>>>(xyz, idx_ptr, w1, b1, gamma1, beta1,
                                 mean1, var1, hhi, hlo);

    mma_gemm<128, 256, 512, 0><<<dim3(NPTS / 128, 2), 256>>>(
        hhi, hlo, w2hi, w2lo, b2, nullptr, nullptr, nullptr, xyz, X_ptr);

    cudaFuncSetAttribute(lift_xform,
                         cudaFuncAttributeMaxDynamicSharedMemorySize, 83456);
    lift_xform<<<NPTS / 16, 256, 83456>>>(
        feat, idx_ptr, xyz, wl, gamma_l, beta_l, mean_l, var_l,
        X_ptr, thi, tlo);

    mma_gemm<64, 128, 1024, 1><<<dim3(NPTS / 64, 1), 256>>>(
        thi, tlo, wfhi, wflo, gamma_f, beta_f, mean_f, var_f, xyz, out);
}

// round 14
// speedup vs baseline: 1.0437x; 1.0437x over previous
#include <cuda_runtime.h>
#include <cuda_bf16.h>
#include <cstdint>
#include <float.h>

#define BB    8
#define NN    2048
#define KK    16
#define CIN   64
#define COUT  128
#define BN_EPS 1e-3f
#define LARGE_DIST 1e9f
#define MARGIN 2e-4f

#define SPLIT 4
#define CAND  (NN / SPLIT)   // 512
#define NPTS  (BB * NN)      // 16384

// ---- global scratch -------------------------------------------------------
__device__ float          g_pd[NPTS * SPLIT * KK];
__device__ int            g_pi[NPTS * SPLIT * KK];
__device__ int            g_idx[NPTS * KK];
__device__ unsigned short g_h_hi[(size_t)NPTS * 512];
__device__ unsigned short g_h_lo[(size_t)NPTS * 512];
__device__ float          g_X[(size_t)NPTS * 256];
__device__ unsigned short g_t_hi[(size_t)NPTS * 1024];
__device__ unsigned short g_t_lo[(size_t)NPTS * 1024];
__device__ unsigned short g_w2t_hi[256 * 512];
__device__ unsigned short g_w2t_lo[256 * 512];
__device__ unsigned short g_wft_hi[128 * 1024];
__device__ unsigned short g_wft_lo[128 * 1024];

// ---- packed fp32x2 helpers ------------------------------------------------
__device__ __forceinline__ unsigned long long pack2(float lo, float hi) {
    unsigned long long r;
    asm("mov.b64 %0, {%1, %2};" : "=l"(r) : "f"(lo), "f"(hi));
    return r;
}
__device__ __forceinline__ float2 unpack2(unsigned long long v) {
    float2 r;
    asm("mov.b64 {%0, %1}, %2;" : "=f"(r.x), "=f"(r.y) : "l"(v));
    return r;
}
__device__ __forceinline__ void ffma2(unsigned long long& a,
                                      unsigned long long x,
                                      unsigned long long y) {
    asm("fma.rn.f32x2 %0, %1, %2, %0;" : "+l"(a) : "l"(x), "l"(y));
}

// ---- mma.sync helpers ------------------------------------------------------
__device__ __forceinline__ uint32_t smem_u32(const void* p) {
    uint32_t a;
    asm("{ .reg .u64 t; cvta.to.shared.u64 t, %1; cvt.u32.u64 %0, t; }"
        : "=r"(a) : "l"(p));
    return a;
}
__device__ __forceinline__ void ldm_x4(uint32_t* r, uint32_t addr) {
    asm volatile("ldmatrix.sync.aligned.m8n8.x4.shared.b16 {%0,%1,%2,%3}, [%4];"
                 : "=r"(r[0]), "=r"(r[1]), "=r"(r[2]), "=r"(r[3]) : "r"(addr));
}
__device__ __forceinline__ void ldm_x2(uint32_t* r, uint32_t addr) {
    asm volatile("ldmatrix.sync.aligned.m8n8.x2.shared.b16 {%0,%1}, [%2];"
                 : "=r"(r[0]), "=r"(r[1]) : "r"(addr));
}
__device__ __forceinline__ void mma_bf16(float* d, const uint32_t* a,
                                         const uint32_t* b) {
    asm volatile(
        "mma.sync.aligned.m16n8k16.row.col.f32.bf16.bf16.f32 "
        "{%0,%1,%2,%3}, {%4,%5,%6,%7}, {%8,%9}, {%0,%1,%2,%3};"
        : "+f"(d[0]), "+f"(d[1]), "+f"(d[2]), "+f"(d[3])
        : "r"(a[0]), "r"(a[1]), "r"(a[2]), "r"(a[3]), "r"(b[0]), "r"(b[1]));
}

// ---------------------------------------------------------------------------
// KNN
// ---------------------------------------------------------------------------
__device__ __forceinline__ void insert16(float* bd, int* bi, float d, int j) {
    bd[KK - 1] = d; bi[KK - 1] = j;
#pragma unroll
    for (int t = KK - 1; t > 0; --t) {
        if (bd[t] < bd[t - 1]) {
            float td = bd[t]; bd[t] = bd[t - 1]; bd[t - 1] = td;
            int   ti = bi[t]; bi[t] = bi[t - 1]; bi[t - 1] = ti;
        }
    }
}

// prune-scan KNN (R10-winning scan body), 256 queries/block to halve the
// per-block staging cost. Hot path = approx dist (norm trick, f32x2);
// on pack hit, EXACT reference distances for all 4 (top_k ordering kept).
__global__ __launch_bounds__(256)
void knn_part(const float* __restrict__ xyz,
              float* __restrict__ pd, int* __restrict__ pi) {
    __shared__ __align__(16) float s_x[NN], s_y[NN], s_z[NN], s_pn[NN], s_pen[NN];
    const int tid = threadIdx.x;
    const int qg  = blockIdx.x >> 2;     // 256-query group
    const int sp  = blockIdx.x & 3;
    const int g   = qg * 256 + tid;
    const int b   = g >> 11;
    const int n   = g & (NN - 1);

    for (int j = tid; j < NN; j += 256) {
        const float* p = xyz + ((size_t)b * NN + j) * 3;
        float x = p[0], y = p[1], z = p[2];
        float pen = (x != 0.0f || y != 0.0f || z != 0.0f) ? 0.0f : LARGE_DIST;
        s_x[j] = x; s_y[j] = y; s_z[j] = z;
        s_pen[j] = pen;
        s_pn[j]  = x * x + y * y + z * z + pen;
    }
    __syncthreads();

    const float* qp = xyz + ((size_t)b * NN + n) * 3;
    const float qx = qp[0], qy = qp[1], qz = qp[2];
    const float qnorm = qx * qx + qy * qy + qz * qz;
    const unsigned long long mx2 = pack2(-2.0f * qx, -2.0f * qx);
    const unsigned long long my2 = pack2(-2.0f * qy, -2.0f * qy);
    const unsigned long long mz2 = pack2(-2.0f * qz, -2.0f * qz);

    float bd[KK]; int bi[KK];
#pragma unroll
    for (int t = 0; t < KK; t++) { bd[t] = FLT_MAX; bi[t] = 0; }
    float boundp = FLT_MAX;

    const int j0 = sp * CAND;
#pragma unroll 4
    for (int jj = 0; jj < CAND; jj += 4) {
        const int j = j0 + jj;
        ulonglong2 Xv = *(const ulonglong2*)&s_x[j];
        ulonglong2 Yv = *(const ulonglong2*)&s_y[j];
        ulonglong2 Zv = *(const ulonglong2*)&s_z[j];
        ulonglong2 Nv = *(const ulonglong2*)&s_pn[j];
        unsigned long long d0 = Nv.x, d1 = Nv.y;
        ffma2(d0, mx2, Xv.x); ffma2(d0, my2, Yv.x); ffma2(d0, mz2, Zv.x);
        ffma2(d1, mx2, Xv.y); ffma2(d1, my2, Yv.y); ffma2(d1, mz2, Zv.y);
        float2 a = unpack2(d0), c = unpack2(d1);
        float mn = fminf(fminf(a.x, a.y), fminf(c.x, c.y));
        if (mn < boundp) {
#pragma unroll
            for (int t4 = 0; t4 < 4; t4++) {
                float px = s_x[j + t4], py = s_y[j + t4], pz = s_z[j + t4];
                float dx = qx - px, dy = qy - py, dz = qz - pz;
                float d = dx * dx + dy * dy + dz * dz + s_pen[j + t4];
                if (d < bd[KK - 1]) insert16(bd, bi, d, j + t4);
            }
            boundp = bd[KK - 1] - qnorm + MARGIN;
        }
    }

    float* po = pd + ((size_t)g * SPLIT + sp) * KK;
    int*   io = pi + ((size_t)g * SPLIT + sp) * KK;
#pragma unroll
    for (int t = 0; t < KK; t++) { po[t] = bd[t]; io[t] = bi[t]; }
}

// 2-phase merge (R11 measured-best): 2 threads/query, each merges 32 partial
// entries (ascending split order), half-0 folds half-1's top-16 via smem.
__global__ __launch_bounds__(256)
void knn_merge(const float* __restrict__ pd, const int* __restrict__ pi,
               int* __restrict__ idx_out) {
    __shared__ float sd[128][17];
    __shared__ int   si[128][17];
    const int tid  = threadIdx.x;
    const int q    = tid >> 1;
    const int half = tid & 1;
    const int g    = blockIdx.x * 128 + q;

    float bd[KK]; int bi[KK];
#pragma unroll
    for (int t = 0; t < KK; t++) { bd[t] = FLT_MAX; bi[t] = 0; }

    const float* pp = pd + (size_t)g * SPLIT * KK + half * 32;
    const int*   ii = pi + (size_t)g * SPLIT * KK + half * 32;
#pragma unroll 4
    for (int c = 0; c < 32; c++) {
        float d = pp[c];
        if (d < bd[KK - 1]) insert16(bd, bi, d, ii[c]);
    }

    if (half) {
#pragma unroll
        for (int t = 0; t < KK; t++) { sd[q][t] = bd[t]; si[q][t] = bi[t]; }
    }
    __syncthreads();
    if (!half) {
#pragma unroll
        for (int c = 0; c < KK; c++) {
            float d = sd[q][c];
            if (d < bd[KK - 1]) insert16(bd, bi, d, si[q][c]);
        }
#pragma unroll
        for (int t = 0; t < KK; t++) idx_out[(size_t)g * KK + t] = bi[t];
    }
}

// ---------------------------------------------------------------------------
// k2: h precompute -> bf16 hi/lo
// ---------------------------------------------------------------------------
__global__ __launch_bounds__(256)
void h_kernel(const float* __restrict__ xyz, const int* __restrict__ idx,
              const float* __restrict__ w1, const float* __restrict__ b1,
              const float* __restrict__ gamma1, const float* __restrict__ beta1,
              const float* __restrict__ mean1, const float* __restrict__ var1,
              unsigned short* __restrict__ Hhi, unsigned short* __restrict__ Hlo) {
    __shared__ float sw[96], sb[32], ssc[32], ssh[32];
    const int tid = threadIdx.x;
    if (tid < 96) sw[tid] = w1[tid];
    if (tid < 32) {
        sb[tid] = b1[tid];
        float sc = gamma1[tid] * rsqrtf(var1[tid] + BN_EPS);
        ssc[tid] = sc;
        ssh[tid] = beta1[tid] - mean1[tid] * sc;
    }
    __syncthreads();

    const int g0 = blockIdx.x * 16;
    const int p  = tid >> 4;
    const int k  = tid & 15;
    const int g  = g0 + p;
    const int b  = g >> 11;
    const int n  = g & (NN - 1);
    const int nbr = idx[(size_t)g * KK + k];

    const float* qp = xyz + ((size_t)b * NN + n) * 3;
    const float* np = xyz + ((size_t)b * NN + nbr) * 3;
    float qx = qp[0], qy = qp[1], qz = qp[2];
    float px = np[0], py = np[1], pz = np[2];
    float nm = (px != 0.0f || py != 0.0f || pz != 0.0f) ? 1.0f : 0.0f;
    float r0 = nm * (px - qx), r1 = nm * (py - qy), r2 = nm * (pz - qz);

    unsigned short hh[32], ll[32];
#pragma unroll
    for (int d = 0; d < 32; d++) {
        float v = r0 * sw[d] + r1 * sw[32 + d] + r2 * sw[64 + d] + sb[d];
        v = fmaxf(v, 0.0f);
        v = v * ssc[d] + ssh[d];
        __nv_bfloat16 hv = __float2bfloat16(v);
        float res = v - __bfloat162float(hv);
        hh[d] = __bfloat16_as_ushort(hv);
        ll[d] = __bfloat16_as_ushort(__float2bfloat16(res));
    }
    size_t off = (size_t)g * 512 + k * 32;
#pragma unroll
    for (int q = 0; q < 4; q++) {
        *(uint4*)(Hhi + off + q * 8) = *(uint4*)&hh[q * 8];
        *(uint4*)(Hlo + off + q * 8) = *(uint4*)&ll[q * 8];
    }
}

// ---------------------------------------------------------------------------
// prep: transpose + bf16-split a weight matrix  W[K][N] -> out[N][K]
// ---------------------------------------------------------------------------
__global__ void prep_bT(const float* __restrict__ W,
                        unsigned short* __restrict__ hi,
                        unsigned short* __restrict__ lo, int K, int N) {
    int i = blockIdx.x * 256 + threadIdx.x;
    if (i >= K * N) return;
    int n = i % N, k = i / N;
    float v = W[i];
    __nv_bfloat16 h = __float2bfloat16(v);
    float r = v - __bfloat162float(h);
    hi[(size_t)n * K + k] = __bfloat16_as_ushort(h);
    lo[(size_t)n * K + k] = __bfloat16_as_ushort(__float2bfloat16(r));
}

// ---------------------------------------------------------------------------
// mma.sync bf16 3-term GEMM
// ---------------------------------------------------------------------------
template<int BM, int NMAT, int KTOT, int EPI>
__global__ __launch_bounds__(256)
void mma_gemm(const unsigned short* __restrict__ Ahi,
              const unsigned short* __restrict__ Alo,
              const unsigned short* __restrict__ Bhi,
              const unsigned short* __restrict__ Blo,
              const float* __restrict__ e0, const float* __restrict__ e1,
              const float* __restrict__ e2, const float* __restrict__ e3,
              const float* __restrict__ xyz, float* __restrict__ C) {
    constexpr int MT = BM / 32;
    constexpr int LDS_H = 40;
    __shared__ __align__(16) unsigned short sAh[BM * LDS_H];
    __shared__ __align__(16) unsigned short sAl[BM * LDS_H];
    __shared__ __align__(16) unsigned short sBh[128 * LDS_H];
    __shared__ __align__(16) unsigned short sBl[128 * LDS_H];

    const int tid  = threadIdx.x;
    const int lane = tid & 31;
    const int wid  = tid >> 5;
    const int wr   = wid >> 2;
    const int wc   = wid & 3;
    const int g0   = blockIdx.x * BM;
    const int col0 = blockIdx.y * 128;

    const uint32_t aHiB = smem_u32(sAh), aLoB = smem_u32(sAl);
    const uint32_t bHiB = smem_u32(sBh), bLoB = smem_u32(sBl);

    float acc[MT][4][4];
#pragma unroll
    for (int m = 0; m < MT; m++)
#pragma unroll
        for (int n = 0; n < 4; n++)
#pragma unroll
            for (int q = 0; q < 4; q++) acc[m][n][q] = 0.0f;

    const int q8 = lane >> 3;
    const int r8 = lane & 7;

    for (int k0 = 0; k0 < KTOT; k0 += 32) {
#pragma unroll
        for (int v = tid; v < BM * 4; v += 256) {
            int row = v >> 2, c8 = (v & 3) * 8;
            int dst = row * LDS_H + c8;
            size_t src = (size_t)(g0 + row) * KTOT + k0 + c8;
            *(uint4*)(sAh + dst) = *(const uint4*)(Ahi + src);
            *(uint4*)(sAl + dst) = *(const uint4*)(Alo + src);
        }
#pragma unroll
        for (int v = tid; v < 512; v += 256) {
            int row = v >> 2, c8 = (v & 3) * 8;
            int dst = row * LDS_H + c8;
            size_t src = (size_t)(col0 + row) * KTOT + k0 + c8;
            *(uint4*)(sBh + dst) = *(const uint4*)(Bhi + src);
            *(uint4*)(sBl + dst) = *(const uint4*)(Blo + src);
        }
        __syncthreads();

#pragma unroll
        for (int ks = 0; ks < 2; ks++) {
            const int kk = ks * 16;
            uint32_t ah[MT][4], al[MT][4];
#pragma unroll
            for (int m = 0; m < MT; m++) {
                int arow = wr * (BM / 2) + m * 16 + (q8 & 1) * 8 + r8;
                int acol = kk + (q8 >> 1) * 8;
                uint32_t off = (uint32_t)(arow * LDS_H + acol) * 2;
                ldm_x4(ah[m], aHiB + off);
                ldm_x4(al[m], aLoB + off);
            }
            uint32_t bh[4][2], bl[4][2];
#pragma unroll
            for (int n = 0; n < 4; n++) {
                int nrow = wc * 32 + n * 8 + r8;
                int ncol = kk + (q8 & 1) * 8;
                uint32_t off = (uint32_t)(nrow * LDS_H + ncol) * 2;
                ldm_x2(bh[n], bHiB + off);
                ldm_x2(bl[n], bLoB + off);
            }
#pragma unroll
            for (int m = 0; m < MT; m++)
#pragma unroll
                for (int n = 0; n < 4; n++) {
                    mma_bf16(acc[m][n], ah[m], bh[n]);
                    mma_bf16(acc[m][n], ah[m], bl[n]);
                    mma_bf16(acc[m][n], al[m], bh[n]);
                }
        }
        __syncthreads();
    }

#pragma unroll
    for (int m = 0; m < MT; m++) {
        int r1 = g0 + wr * (BM / 2) + m * 16 + (lane >> 2);
        int r2 = r1 + 8;
        float m1 = 1.0f, m2 = 1.0f;
        if (EPI == 1) {
            const float* p1 = xyz + (size_t)r1 * 3;
            const float* p2 = xyz + (size_t)r2 * 3;
            m1 = (p1[0] != 0.0f || p1[1] != 0.0f || p1[2] != 0.0f) ? 1.0f : 0.0f;
            m2 = (p2[0] != 0.0f || p2[1] != 0.0f || p2[2] != 0.0f) ? 1.0f : 0.0f;
        }
#pragma unroll
        for (int n = 0; n < 4; n++) {
            int c = col0 + wc * 32 + n * 8 + (lane & 3) * 2;
            float v0 = acc[m][n][0], v1 = acc[m][n][1];
            float v2 = acc[m][n][2], v3 = acc[m][n][3];
            if (EPI == 0) {
                float bb0 = e0[c], bb1 = e0[c + 1];
                v0 += bb0; v1 += bb1; v2 += bb0; v3 += bb1;
            } else {
                float sc0 = e0[c] * rsqrtf(e3[c] + BN_EPS);
                float sh0 = e1[c] - e2[c] * sc0;
                float sc1 = e0[c + 1] * rsqrtf(e3[c + 1] + BN_EPS);
                float sh1 = e1[c + 1] - e2[c + 1] * sc1;
                v0 = fmaxf(v0 * sc0 + sh0, 0.0f) * m1;
                v1 = fmaxf(v1 * sc1 + sh1, 0.0f) * m1;
                v2 = fmaxf(v2 * sc0 + sh0, 0.0f) * m2;
                v3 = fmaxf(v3 * sc1 + sh1, 0.0f) * m2;
            }
            *(float2*)(C + (size_t)r1 * NMAT + c) = make_float2(v0, v1);
            *(float2*)(C + (size_t)r2 * NMAT + c) = make_float2(v2, v3);
        }
    }
}

// ---------------------------------------------------------------------------
// FUSED k4+k5: lifted (smem only) -> transformed = X @ lifted -> bf16 hi/lo.
// ---------------------------------------------------------------------------
__global__ __launch_bounds__(256)
void lift_xform(const float* __restrict__ feat, const int* __restrict__ idx,
                const float* __restrict__ xyz, const float* __restrict__ wl,
                const float* __restrict__ gamma_l, const float* __restrict__ beta_l,
                const float* __restrict__ mean_l, const float* __restrict__ var_l,
                const float* __restrict__ Xg,
                unsigned short* __restrict__ Thi,
                unsigned short* __restrict__ Tlo) {
    extern __shared__ float sm[];
    float* As    = sm;              // [64][256] featT; later sL[16*1024]
    float* Bs    = sm + 16384;      // [64][64] wl; later sX[16*256]
    float* smask = sm + 20480;      // [256]
    float* ssc   = sm + 20736;      // [64]
    float* ssh   = sm + 20800;      // [64]

    const int tid  = threadIdx.x;
    const int g0   = blockIdx.x * 16;
    const int row0 = blockIdx.x * 256;

    {
        int grow = row0 + tid;
        int nbr  = idx[grow];
        int b    = grow >> 15;
        const float* np = xyz + ((size_t)(b << 11) + nbr) * 3;
        smask[tid] = (np[0] != 0.0f || np[1] != 0.0f || np[2] != 0.0f) ? 1.0f : 0.0f;
        if (tid < 64) {
            float sc = gamma_l[tid] * rsqrtf(var_l[tid] + BN_EPS);
            ssc[tid] = sc;
            ssh[tid] = beta_l[tid] - mean_l[tid] * sc;
        }
    }
    {
        int kr = tid >> 4;
        int cc = (tid & 15) * 4;
#pragma unroll
        for (int h2 = 0; h2 < 4; h2++)
            *(float4*)&Bs[(kr + h2 * 16) * 64 + cc] =
                *(const float4*)(wl + (size_t)(kr + h2 * 16) * 64 + cc);
    }
    {
        int cc = (tid & 15) * 4;
#pragma unroll
        for (int h2 = 0; h2 < 16; h2++) {
            int r    = (tid >> 4) + h2 * 16;
            int grow = row0 + r;
            int nbr  = idx[grow];
            int b    = grow >> 15;
            float4 f = *(const float4*)(feat + ((size_t)(b << 11) + nbr) * 64 + cc);
            As[(cc + 0) * 256 + r] = f.x;
            As[(cc + 1) * 256 + r] = f.y;
            As[(cc + 2) * 256 + r] = f.z;
            As[(cc + 3) * 256 + r] = f.w;
        }
    }
    __syncthreads();

    const int tx = tid & 7;
    const int ty = tid >> 3;
    unsigned long long acc1[8][4];
#pragma unroll
    for (int i = 0; i < 8; i++)
#pragma unroll
        for (int q = 0; q < 4; q++) acc1[i][q] = 0ull;

#pragma unroll 8
    for (int kk = 0; kk < 64; kk++) {
        float a[8];
        *(float4*)&a[0] = *(const float4*)&As[kk * 256 + ty * 8];
        *(float4*)&a[4] = *(const float4*)&As[kk * 256 + ty * 8 + 4];
        ulonglong2 bA = *(const ulonglong2*)&Bs[kk * 64 + tx * 8];
        ulonglong2 bB = *(const ulonglong2*)&Bs[kk * 64 + tx * 8 + 4];
#pragma unroll
        for (int i = 0; i < 8; i++) {
            unsigned long long a2 = pack2(a[i], a[i]);
            ffma2(acc1[i][0], a2, bA.x);
            ffma2(acc1[i][1], a2, bA.y);
            ffma2(acc1[i][2], a2, bB.x);
            ffma2(acc1[i][3], a2, bB.y);
        }
    }
    __syncthreads();   // all As/Bs reads done -> overlay

#pragma unroll
    for (int i = 0; i < 8; i++) {
        int rloc = ty * 8 + i;
        float m  = smask[rloc];
        float v[8];
#pragma unroll
        for (int q = 0; q < 8; q++) {
            float2 p = unpack2(acc1[i][q >> 1]);
            int nc = tx * 8 + q;
            float x = ((q & 1) ? p.y : p.x) * ssc[nc] + ssh[nc];
            v[q] = fmaxf(x, 0.0f) * m;
        }
        float* cp = As + rloc * 64 + tx * 8;
        *(float4*)cp       = make_float4(v[0], v[1], v[2], v[3]);
        *(float4*)(cp + 4) = make_float4(v[4], v[5], v[6], v[7]);
    }
    for (int e = tid * 4; e < 4096; e += 1024)
        *(float4*)&Bs[e] = *(const float4*)(Xg + (size_t)g0 * 256 + e);
    __syncthreads();

    const int p = tid >> 4;
    const int i = tid & 15;

    float xr[16];
    {
        const float4* xp = (const float4*)&Bs[p * 256 + i * 16];
#pragma unroll
        for (int q = 0; q < 4; q++) *(float4*)&xr[q * 4] = xp[q];
    }

    unsigned long long acc[32];
#pragma unroll
    for (int q = 0; q < 32; q++) acc[q] = 0ull;

#pragma unroll
    for (int j = 0; j < 16; j++) {
        unsigned long long xv = pack2(xr[j], xr[j]);
        const ulonglong2* lp = (const ulonglong2*)&As[p * 1024 + j * 64];
#pragma unroll
        for (int q = 0; q < 16; q++) {
            ulonglong2 lv = lp[q];
            ffma2(acc[2 * q],     xv, lv.x);
            ffma2(acc[2 * q + 1], xv, lv.y);
        }
    }

    unsigned short hh[64], ll[64];
#pragma unroll
    for (int q = 0; q < 32; q++) {
        float2 a = unpack2(acc[q]);
        __nv_bfloat16 h0 = __float2bfloat16(a.x);
        __nv_bfloat16 h1 = __float2bfloat16(a.y);
        hh[2 * q]     = __bfloat16_as_ushort(h0);
        hh[2 * q + 1] = __bfloat16_as_ushort(h1);
        ll[2 * q]     = __bfloat16_as_ushort(__float2bfloat16(a.x - __bfloat162float(h0)));
        ll[2 * q + 1] = __bfloat16_as_ushort(__float2bfloat16(a.y - __bfloat162float(h1)));
    }
    size_t off = (size_t)(g0 + p) * 1024 + i * 64;
#pragma unroll
    for (int q = 0; q < 8; q++) {
        *(uint4*)(Thi + off + q * 8) = *(uint4*)&hh[q * 8];
        *(uint4*)(Tlo + off + q * 8) = *(uint4*)&ll[q * 8];
    }
}

// ---------------------------------------------------------------------------
extern "C" void kernel_launch(void* const* d_in, const int* in_sizes, int n_in,
                              void* d_out, int out_size) {
    const float* xyz     = (const float*)d_in[0];
    const float* feat    = (const float*)d_in[1];
    const float* w1      = (const float*)d_in[2];
    const float* b1      = (const float*)d_in[3];
    const float* gamma1  = (const float*)d_in[4];
    const float* beta1   = (const float*)d_in[5];
    const float* mean1   = (const float*)d_in[6];
    const float* var1    = (const float*)d_in[7];
    const float* w2      = (const float*)d_in[8];
    const float* b2      = (const float*)d_in[9];
    const float* wl      = (const float*)d_in[10];
    const float* gamma_l = (const float*)d_in[11];
    const float* beta_l  = (const float*)d_in[12];
    const float* mean_l  = (const float*)d_in[13];
    const float* var_l   = (const float*)d_in[14];
    const float* wf      = (const float*)d_in[15];
    const float* gamma_f = (const float*)d_in[16];
    const float* beta_f  = (const float*)d_in[17];
    const float* mean_f  = (const float*)d_in[18];
    const float* var_f   = (const float*)d_in[19];
    float* out = (float*)d_out;

    float *pd_ptr, *X_ptr;
    int *pi_ptr, *idx_ptr;
    unsigned short *hhi, *hlo, *thi, *tlo, *w2hi, *w2lo, *wfhi, *wflo;
    cudaGetSymbolAddress((void**)&pd_ptr, g_pd);
    cudaGetSymbolAddress((void**)&pi_ptr, g_pi);
    cudaGetSymbolAddress((void**)&idx_ptr, g_idx);
    cudaGetSymbolAddress((void**)&hhi, g_h_hi);
    cudaGetSymbolAddress((void**)&hlo, g_h_lo);
    cudaGetSymbolAddress((void**)&X_ptr, g_X);
    cudaGetSymbolAddress((void**)&thi, g_t_hi);
    cudaGetSymbolAddress((void**)&tlo, g_t_lo);
    cudaGetSymbolAddress((void**)&w2hi, g_w2t_hi);
    cudaGetSymbolAddress((void**)&w2lo, g_w2t_lo);
    cudaGetSymbolAddress((void**)&wfhi, g_wft_hi);
    cudaGetSymbolAddress((void**)&wflo, g_wft_lo);

    knn_part<<<(NPTS / 256) * SPLIT, 256>>>(xyz, pd_ptr, pi_ptr);
    prep_bT<<<(512 * 256 + 255) / 256, 256>>>(w2, w2hi, w2lo, 512, 256);
    prep_bT<<<(1024 * 128 + 255) / 256, 256>>>(wf, wfhi, wflo, 1024, 128);
    knn_merge<<<NPTS / 128, 256>>>(pd_ptr, pi_ptr, idx_ptr);

    h_kernel<<<NPTS / 16, 256>>>(xyz, idx_ptr, w1, b1, gamma1, beta1,
                                 mean1, var1, hhi, hlo);

    mma_gemm<128, 256, 512, 0><<<dim3(NPTS / 128, 2), 256>>>(
        hhi, hlo, w2hi, w2lo, b2, nullptr, nullptr, nullptr, xyz, X_ptr);

    cudaFuncSetAttribute(lift_xform,
                         cudaFuncAttributeMaxDynamicSharedMemorySize, 83456);
    lift_xform<<<NPTS / 16, 256, 83456>>>(
        feat, idx_ptr, xyz, wl, gamma_l, beta_l, mean_l, var_l,
        X_ptr, thi, tlo);

    mma_gemm<64, 128, 1024, 1><<<dim3(NPTS / 64, 1), 256>>>(
        thi, tlo, wfhi, wflo, gamma_f, beta_f, mean_f, var_f, xyz, out);
}

// round 15
// speedup vs baseline: 1.1698x; 1.1208x over previous
#include <cuda_runtime.h>
#include <cuda_bf16.h>
#include <cstdint>
#include <float.h>

#define BB    8
#define NN    2048
#define KK    16
#define CIN   64
#define COUT  128
#define BN_EPS 1e-3f
#define LARGE_DIST 1e9f
#define MARGIN 2e-4f

#define SPLIT 4
#define CAND  (NN / SPLIT)   // 512
#define NPTS  (BB * NN)      // 16384

// ---- global scratch -------------------------------------------------------
__device__ float          g_pd[NPTS * SPLIT * KK];
__device__ int            g_pi[NPTS * SPLIT * KK];
__device__ int            g_idx[NPTS * KK];
__device__ unsigned short g_h_hi[(size_t)NPTS * 512];
__device__ unsigned short g_h_lo[(size_t)NPTS * 512];
__device__ float          g_X[(size_t)NPTS * 256];
__device__ float          g_L0[(size_t)NPTS * 64];
__device__ unsigned short g_t_hi[(size_t)NPTS * 1024];
__device__ unsigned short g_t_lo[(size_t)NPTS * 1024];
__device__ unsigned short g_w2t_hi[256 * 512];
__device__ unsigned short g_w2t_lo[256 * 512];
__device__ unsigned short g_wft_hi[128 * 1024];
__device__ unsigned short g_wft_lo[128 * 1024];

// ---- packed fp32x2 helpers ------------------------------------------------
__device__ __forceinline__ unsigned long long pack2(float lo, float hi) {
    unsigned long long r;
    asm("mov.b64 %0, {%1, %2};" : "=l"(r) : "f"(lo), "f"(hi));
    return r;
}
__device__ __forceinline__ float2 unpack2(unsigned long long v) {
    float2 r;
    asm("mov.b64 {%0, %1}, %2;" : "=f"(r.x), "=f"(r.y) : "l"(v));
    return r;
}
__device__ __forceinline__ void ffma2(unsigned long long& a,
                                      unsigned long long x,
                                      unsigned long long y) {
    asm("fma.rn.f32x2 %0, %1, %2, %0;" : "+l"(a) : "l"(x), "l"(y));
}

// ---- mma.sync helpers ------------------------------------------------------
__device__ __forceinline__ uint32_t smem_u32(const void* p) {
    uint32_t a;
    asm("{ .reg .u64 t; cvta.to.shared.u64 t, %1; cvt.u32.u64 %0, t; }"
        : "=r"(a) : "l"(p));
    return a;
}
__device__ __forceinline__ void ldm_x4(uint32_t* r, uint32_t addr) {
    asm volatile("ldmatrix.sync.aligned.m8n8.x4.shared.b16 {%0,%1,%2,%3}, [%4];"
                 : "=r"(r[0]), "=r"(r[1]), "=r"(r[2]), "=r"(r[3]) : "r"(addr));
}
__device__ __forceinline__ void ldm_x2(uint32_t* r, uint32_t addr) {
    asm volatile("ldmatrix.sync.aligned.m8n8.x2.shared.b16 {%0,%1}, [%2];"
                 : "=r"(r[0]), "=r"(r[1]) : "r"(addr));
}
__device__ __forceinline__ void mma_bf16(float* d, const uint32_t* a,
                                         const uint32_t* b) {
    asm volatile(
        "mma.sync.aligned.m16n8k16.row.col.f32.bf16.bf16.f32 "
        "{%0,%1,%2,%3}, {%4,%5,%6,%7}, {%8,%9}, {%0,%1,%2,%3};"
        : "+f"(d[0]), "+f"(d[1]), "+f"(d[2]), "+f"(d[3])
        : "r"(a[0]), "r"(a[1]), "r"(a[2]), "r"(a[3]), "r"(b[0]), "r"(b[1]));
}

// ---------------------------------------------------------------------------
// KNN
// ---------------------------------------------------------------------------
__device__ __forceinline__ void insert16(float* bd, int* bi, float d, int j) {
    bd[KK - 1] = d; bi[KK - 1] = j;
#pragma unroll
    for (int t = KK - 1; t > 0; --t) {
        if (bd[t] < bd[t - 1]) {
            float td = bd[t]; bd[t] = bd[t - 1]; bd[t - 1] = td;
            int   ti = bi[t]; bi[t] = bi[t - 1]; bi[t - 1] = ti;
        }
    }
}

__global__ __launch_bounds__(256)
void knn_part(const float* __restrict__ xyz,
              float* __restrict__ pd, int* __restrict__ pi) {
    __shared__ __align__(16) float s_x[NN], s_y[NN], s_z[NN], s_pn[NN], s_pen[NN];
    const int tid = threadIdx.x;
    const int qg  = blockIdx.x >> 2;
    const int sp  = blockIdx.x & 3;
    const int g   = qg * 256 + tid;
    const int b   = g >> 11;
    const int n   = g & (NN - 1);

    for (int j = tid; j < NN; j += 256) {
        const float* p = xyz + ((size_t)b * NN + j) * 3;
        float x = p[0], y = p[1], z = p[2];
        float pen = (x != 0.0f || y != 0.0f || z != 0.0f) ? 0.0f : LARGE_DIST;
        s_x[j] = x; s_y[j] = y; s_z[j] = z;
        s_pen[j] = pen;
        s_pn[j]  = x * x + y * y + z * z + pen;
    }
    __syncthreads();

    const float* qp = xyz + ((size_t)b * NN + n) * 3;
    const float qx = qp[0], qy = qp[1], qz = qp[2];
    const float qnorm = qx * qx + qy * qy + qz * qz;
    const unsigned long long mx2 = pack2(-2.0f * qx, -2.0f * qx);
    const unsigned long long my2 = pack2(-2.0f * qy, -2.0f * qy);
    const unsigned long long mz2 = pack2(-2.0f * qz, -2.0f * qz);

    float bd[KK]; int bi[KK];
#pragma unroll
    for (int t = 0; t < KK; t++) { bd[t] = FLT_MAX; bi[t] = 0; }
    float boundp = FLT_MAX;

    const int j0 = sp * CAND;
#pragma unroll 4
    for (int jj = 0; jj < CAND; jj += 4) {
        const int j = j0 + jj;
        ulonglong2 Xv = *(const ulonglong2*)&s_x[j];
        ulonglong2 Yv = *(const ulonglong2*)&s_y[j];
        ulonglong2 Zv = *(const ulonglong2*)&s_z[j];
        ulonglong2 Nv = *(const ulonglong2*)&s_pn[j];
        unsigned long long d0 = Nv.x, d1 = Nv.y;
        ffma2(d0, mx2, Xv.x); ffma2(d0, my2, Yv.x); ffma2(d0, mz2, Zv.x);
        ffma2(d1, mx2, Xv.y); ffma2(d1, my2, Yv.y); ffma2(d1, mz2, Zv.y);
        float2 a = unpack2(d0), c = unpack2(d1);
        float mn = fminf(fminf(a.x, a.y), fminf(c.x, c.y));
        if (mn < boundp) {
#pragma unroll
            for (int t4 = 0; t4 < 4; t4++) {
                float px = s_x[j + t4], py = s_y[j + t4], pz = s_z[j + t4];
                float dx = qx - px, dy = qy - py, dz = qz - pz;
                float d = dx * dx + dy * dy + dz * dz + s_pen[j + t4];
                if (d < bd[KK - 1]) insert16(bd, bi, d, j + t4);
            }
            boundp = bd[KK - 1] - qnorm + MARGIN;
        }
    }

    float* po = pd + ((size_t)g * SPLIT + sp) * KK;
    int*   io = pi + ((size_t)g * SPLIT + sp) * KK;
#pragma unroll
    for (int t = 0; t < KK; t++) { po[t] = bd[t]; io[t] = bi[t]; }
}

__global__ __launch_bounds__(256)
void knn_merge(const float* __restrict__ pd, const int* __restrict__ pi,
               int* __restrict__ idx_out) {
    __shared__ float sd[128][17];
    __shared__ int   si[128][17];
    const int tid  = threadIdx.x;
    const int q    = tid >> 1;
    const int half = tid & 1;
    const int g    = blockIdx.x * 128 + q;

    float bd[KK]; int bi[KK];
#pragma unroll
    for (int t = 0; t < KK; t++) { bd[t] = FLT_MAX; bi[t] = 0; }

    const float* pp = pd + (size_t)g * SPLIT * KK + half * 32;
    const int*   ii = pi + (size_t)g * SPLIT * KK + half * 32;
#pragma unroll 4
    for (int c = 0; c < 32; c++) {
        float d = pp[c];
        if (d < bd[KK - 1]) insert16(bd, bi, d, ii[c]);
    }

    if (half) {
#pragma unroll
        for (int t = 0; t < KK; t++) { sd[q][t] = bd[t]; si[q][t] = bi[t]; }
    }
    __syncthreads();
    if (!half) {
#pragma unroll
        for (int c = 0; c < KK; c++) {
            float d = sd[q][c];
            if (d < bd[KK - 1]) insert16(bd, bi, d, si[q][c]);
        }
#pragma unroll
        for (int t = 0; t < KK; t++) idx_out[(size_t)g * KK + t] = bi[t];
    }
}

// ---------------------------------------------------------------------------
// k2: h precompute -> bf16 hi/lo
// ---------------------------------------------------------------------------
__global__ __launch_bounds__(256)
void h_kernel(const float* __restrict__ xyz, const int* __restrict__ idx,
              const float* __restrict__ w1, const float* __restrict__ b1,
              const float* __restrict__ gamma1, const float* __restrict__ beta1,
              const float* __restrict__ mean1, const float* __restrict__ var1,
              unsigned short* __restrict__ Hhi, unsigned short* __restrict__ Hlo) {
    __shared__ float sw[96], sb[32], ssc[32], ssh[32];
    const int tid = threadIdx.x;
    if (tid < 96) sw[tid] = w1[tid];
    if (tid < 32) {
        sb[tid] = b1[tid];
        float sc = gamma1[tid] * rsqrtf(var1[tid] + BN_EPS);
        ssc[tid] = sc;
        ssh[tid] = beta1[tid] - mean1[tid] * sc;
    }
    __syncthreads();

    const int g0 = blockIdx.x * 16;
    const int p  = tid >> 4;
    const int k  = tid & 15;
    const int g  = g0 + p;
    const int b  = g >> 11;
    const int n  = g & (NN - 1);
    const int nbr = idx[(size_t)g * KK + k];

    const float* qp = xyz + ((size_t)b * NN + n) * 3;
    const float* np = xyz + ((size_t)b * NN + nbr) * 3;
    float qx = qp[0], qy = qp[1], qz = qp[2];
    float px = np[0], py = np[1], pz = np[2];
    float nm = (px != 0.0f || py != 0.0f || pz != 0.0f) ? 1.0f : 0.0f;
    float r0 = nm * (px - qx), r1 = nm * (py - qy), r2 = nm * (pz - qz);

    unsigned short hh[32], ll[32];
#pragma unroll
    for (int d = 0; d < 32; d++) {
        float v = r0 * sw[d] + r1 * sw[32 + d] + r2 * sw[64 + d] + sb[d];
        v = fmaxf(v, 0.0f);
        v = v * ssc[d] + ssh[d];
        __nv_bfloat16 hv = __float2bfloat16(v);
        float res = v - __bfloat162float(hv);
        hh[d] = __bfloat16_as_ushort(hv);
        ll[d] = __bfloat16_as_ushort(__float2bfloat16(res));
    }
    size_t off = (size_t)g * 512 + k * 32;
#pragma unroll
    for (int q = 0; q < 4; q++) {
        *(uint4*)(Hhi + off + q * 8) = *(uint4*)&hh[q * 8];
        *(uint4*)(Hlo + off + q * 8) = *(uint4*)&ll[q * 8];
    }
}

// ---------------------------------------------------------------------------
// prep: transpose + bf16-split a weight matrix  W[K][N] -> out[N][K]
// ---------------------------------------------------------------------------
__global__ void prep_bT(const float* __restrict__ W,
                        unsigned short* __restrict__ hi,
                        unsigned short* __restrict__ lo, int K, int N) {
    int i = blockIdx.x * 256 + threadIdx.x;
    if (i >= K * N) return;
    int n = i % N, k = i / N;
    float v = W[i];
    __nv_bfloat16 h = __float2bfloat16(v);
    float r = v - __bfloat162float(h);
    hi[(size_t)n * K + k] = __bfloat16_as_ushort(h);
    lo[(size_t)n * K + k] = __bfloat16_as_ushort(__float2bfloat16(r));
}

// ---------------------------------------------------------------------------
// lift0: L0[p] = relu(BN(feat[p] @ wl)) * mask[p]   (PER-POINT, 16384 rows)
// 256 rows/block, 8x8 micro, ffma2.
// ---------------------------------------------------------------------------
__global__ __launch_bounds__(256)
void lift0_kernel(const float* __restrict__ feat, const float* __restrict__ xyz,
                  const float* __restrict__ wl,
                  const float* __restrict__ gamma_l, const float* __restrict__ beta_l,
                  const float* __restrict__ mean_l, const float* __restrict__ var_l,
                  float* __restrict__ L0) {
    extern __shared__ float sm0[];
    float* As    = sm0;             // [64][256] featT
    float* Bs    = sm0 + 16384;     // [64][64] wl
    float* smask = sm0 + 20480;     // [256]
    float* ssc   = sm0 + 20736;     // [64]
    float* ssh   = sm0 + 20800;     // [64]

    const int tid  = threadIdx.x;
    const int row0 = blockIdx.x * 256;    // point index

    {
        const float* np = xyz + (size_t)(row0 + tid) * 3;
        smask[tid] = (np[0] != 0.0f || np[1] != 0.0f || np[2] != 0.0f) ? 1.0f : 0.0f;
        if (tid < 64) {
            float sc = gamma_l[tid] * rsqrtf(var_l[tid] + BN_EPS);
            ssc[tid] = sc;
            ssh[tid] = beta_l[tid] - mean_l[tid] * sc;
        }
    }
    {
        int kr = tid >> 4;
        int cc = (tid & 15) * 4;
#pragma unroll
        for (int h2 = 0; h2 < 4; h2++)
            *(float4*)&Bs[(kr + h2 * 16) * 64 + cc] =
                *(const float4*)(wl + (size_t)(kr + h2 * 16) * 64 + cc);
    }
    {
        int cc = (tid & 15) * 4;
#pragma unroll
        for (int h2 = 0; h2 < 16; h2++) {
            int r = (tid >> 4) + h2 * 16;
            float4 f = *(const float4*)(feat + (size_t)(row0 + r) * 64 + cc);
            As[(cc + 0) * 256 + r] = f.x;
            As[(cc + 1) * 256 + r] = f.y;
            As[(cc + 2) * 256 + r] = f.z;
            As[(cc + 3) * 256 + r] = f.w;
        }
    }
    __syncthreads();

    const int tx = tid & 7;
    const int ty = tid >> 3;
    unsigned long long acc[8][4];
#pragma unroll
    for (int i = 0; i < 8; i++)
#pragma unroll
        for (int q = 0; q < 4; q++) acc[i][q] = 0ull;

#pragma unroll 8
    for (int kk = 0; kk < 64; kk++) {
        float a[8];
        *(float4*)&a[0] = *(const float4*)&As[kk * 256 + ty * 8];
        *(float4*)&a[4] = *(const float4*)&As[kk * 256 + ty * 8 + 4];
        ulonglong2 bA = *(const ulonglong2*)&Bs[kk * 64 + tx * 8];
        ulonglong2 bB = *(const ulonglong2*)&Bs[kk * 64 + tx * 8 + 4];
#pragma unroll
        for (int i = 0; i < 8; i++) {
            unsigned long long a2 = pack2(a[i], a[i]);
            ffma2(acc[i][0], a2, bA.x);
            ffma2(acc[i][1], a2, bA.y);
            ffma2(acc[i][2], a2, bB.x);
            ffma2(acc[i][3], a2, bB.y);
        }
    }

#pragma unroll
    for (int i = 0; i < 8; i++) {
        int rloc = ty * 8 + i;
        float m  = smask[rloc];
        float v[8];
#pragma unroll
        for (int q = 0; q < 8; q++) {
            float2 p = unpack2(acc[i][q >> 1]);
            int nc = tx * 8 + q;
            float x = ((q & 1) ? p.y : p.x) * ssc[nc] + ssh[nc];
            v[q] = fmaxf(x, 0.0f) * m;
        }
        float* cp = L0 + (size_t)(row0 + rloc) * 64 + tx * 8;
        *(float4*)cp       = make_float4(v[0], v[1], v[2], v[3]);
        *(float4*)(cp + 4) = make_float4(v[4], v[5], v[6], v[7]);
    }
}

// ---------------------------------------------------------------------------
// mma.sync bf16 3-term GEMM (unchanged)
// ---------------------------------------------------------------------------
template<int BM, int NMAT, int KTOT, int EPI>
__global__ __launch_bounds__(256)
void mma_gemm(const unsigned short* __restrict__ Ahi,
              const unsigned short* __restrict__ Alo,
              const unsigned short* __restrict__ Bhi,
              const unsigned short* __restrict__ Blo,
              const float* __restrict__ e0, const float* __restrict__ e1,
              const float* __restrict__ e2, const float* __restrict__ e3,
              const float* __restrict__ xyz, float* __restrict__ C) {
    constexpr int MT = BM / 32;
    constexpr int LDS_H = 40;
    __shared__ __align__(16) unsigned short sAh[BM * LDS_H];
    __shared__ __align__(16) unsigned short sAl[BM * LDS_H];
    __shared__ __align__(16) unsigned short sBh[128 * LDS_H];
    __shared__ __align__(16) unsigned short sBl[128 * LDS_H];

    const int tid  = threadIdx.x;
    const int lane = tid & 31;
    const int wid  = tid >> 5;
    const int wr   = wid >> 2;
    const int wc   = wid & 3;
    const int g0   = blockIdx.x * BM;
    const int col0 = blockIdx.y * 128;

    const uint32_t aHiB = smem_u32(sAh), aLoB = smem_u32(sAl);
    const uint32_t bHiB = smem_u32(sBh), bLoB = smem_u32(sBl);

    float acc[MT][4][4];
#pragma unroll
    for (int m = 0; m < MT; m++)
#pragma unroll
        for (int n = 0; n < 4; n++)
#pragma unroll
            for (int q = 0; q < 4; q++) acc[m][n][q] = 0.0f;

    const int q8 = lane >> 3;
    const int r8 = lane & 7;

    for (int k0 = 0; k0 < KTOT; k0 += 32) {
#pragma unroll
        for (int v = tid; v < BM * 4; v += 256) {
            int row = v >> 2, c8 = (v & 3) * 8;
            int dst = row * LDS_H + c8;
            size_t src = (size_t)(g0 + row) * KTOT + k0 + c8;
            *(uint4*)(sAh + dst) = *(const uint4*)(Ahi + src);
            *(uint4*)(sAl + dst) = *(const uint4*)(Alo + src);
        }
#pragma unroll
        for (int v = tid; v < 512; v += 256) {
            int row = v >> 2, c8 = (v & 3) * 8;
            int dst = row * LDS_H + c8;
            size_t src = (size_t)(col0 + row) * KTOT + k0 + c8;
            *(uint4*)(sBh + dst) = *(const uint4*)(Bhi + src);
            *(uint4*)(sBl + dst) = *(const uint4*)(Blo + src);
        }
        __syncthreads();

#pragma unroll
        for (int ks = 0; ks < 2; ks++) {
            const int kk = ks * 16;
            uint32_t ah[MT][4], al[MT][4];
#pragma unroll
            for (int m = 0; m < MT; m++) {
                int arow = wr * (BM / 2) + m * 16 + (q8 & 1) * 8 + r8;
                int acol = kk + (q8 >> 1) * 8;
                uint32_t off = (uint32_t)(arow * LDS_H + acol) * 2;
                ldm_x4(ah[m], aHiB + off);
                ldm_x4(al[m], aLoB + off);
            }
            uint32_t bh[4][2], bl[4][2];
#pragma unroll
            for (int n = 0; n < 4; n++) {
                int nrow = wc * 32 + n * 8 + r8;
                int ncol = kk + (q8 & 1) * 8;
                uint32_t off = (uint32_t)(nrow * LDS_H + ncol) * 2;
                ldm_x2(bh[n], bHiB + off);
                ldm_x2(bl[n], bLoB + off);
            }
#pragma unroll
            for (int m = 0; m < MT; m++)
#pragma unroll
                for (int n = 0; n < 4; n++) {
                    mma_bf16(acc[m][n], ah[m], bh[n]);
                    mma_bf16(acc[m][n], ah[m], bl[n]);
                    mma_bf16(acc[m][n], al[m], bh[n]);
                }
        }
        __syncthreads();
    }

#pragma unroll
    for (int m = 0; m < MT; m++) {
        int r1 = g0 + wr * (BM / 2) + m * 16 + (lane >> 2);
        int r2 = r1 + 8;
        float m1 = 1.0f, m2 = 1.0f;
        if (EPI == 1) {
            const float* p1 = xyz + (size_t)r1 * 3;
            const float* p2 = xyz + (size_t)r2 * 3;
            m1 = (p1[0] != 0.0f || p1[1] != 0.0f || p1[2] != 0.0f) ? 1.0f : 0.0f;
            m2 = (p2[0] != 0.0f || p2[1] != 0.0f || p2[2] != 0.0f) ? 1.0f : 0.0f;
        }
#pragma unroll
        for (int n = 0; n < 4; n++) {
            int c = col0 + wc * 32 + n * 8 + (lane & 3) * 2;
            float v0 = acc[m][n][0], v1 = acc[m][n][1];
            float v2 = acc[m][n][2], v3 = acc[m][n][3];
            if (EPI == 0) {
                float bb0 = e0[c], bb1 = e0[c + 1];
                v0 += bb0; v1 += bb1; v2 += bb0; v3 += bb1;
            } else {
                float sc0 = e0[c] * rsqrtf(e3[c] + BN_EPS);
                float sh0 = e1[c] - e2[c] * sc0;
                float sc1 = e0[c + 1] * rsqrtf(e3[c + 1] + BN_EPS);
                float sh1 = e1[c + 1] - e2[c + 1] * sc1;
                v0 = fmaxf(v0 * sc0 + sh0, 0.0f) * m1;
                v1 = fmaxf(v1 * sc1 + sh1, 0.0f) * m1;
                v2 = fmaxf(v2 * sc0 + sh0, 0.0f) * m2;
                v3 = fmaxf(v3 * sc1 + sh1, 0.0f) * m2;
            }
            *(float2*)(C + (size_t)r1 * NMAT + c) = make_float2(v0, v1);
            *(float2*)(C + (size_t)r2 * NMAT + c) = make_float2(v2, v3);
        }
    }
}

// ---------------------------------------------------------------------------
// xform_gather: gather L0 rows + transformed = X @ lifted -> bf16 hi/lo.
// 16 points/block (256 neighbor rows), 256 threads.
// ---------------------------------------------------------------------------
__global__ __launch_bounds__(256)
void xform_gather(const int* __restrict__ idx, const float* __restrict__ L0,
                  const float* __restrict__ Xg,
                  unsigned short* __restrict__ Thi,
                  unsigned short* __restrict__ Tlo) {
    extern __shared__ float sm[];
    float* sL   = sm;               // [256][64] gathered lifted rows
    float* sX   = sm + 16384;       // [16][256]
    int*   sidx = (int*)(sm + 20480); // [256]
    // 20736 floats + 256 int = 83968 B

    const int tid  = threadIdx.x;
    const int g0   = blockIdx.x * 16;
    const int row0 = blockIdx.x * 256;
    const int bbase = (g0 >> 11) << 11;   // batch * 2048

    sidx[tid] = idx[row0 + tid];
    for (int e = tid * 4; e < 4096; e += 1024)
        *(float4*)&sX[e] = *(const float4*)(Xg + (size_t)g0 * 256 + e);
    __syncthreads();

    // gather: 4 threads per row (64B coalesced chunks), 64 rows per pass
    {
        const int rsub = tid >> 2;        // 0..63
        const int c0   = (tid & 3) * 4;   // 0,4,8,12
#pragma unroll
        for (int rc = 0; rc < 4; rc++) {
            int rloc = rc * 64 + rsub;
            size_t lrow = (size_t)(bbase + sidx[rloc]) * 64;
#pragma unroll
            for (int cc = 0; cc < 4; cc++) {
                int c = c0 + cc * 16;
                *(float4*)&sL[rloc * 64 + c] = *(const float4*)(L0 + lrow + c);
            }
        }
    }
    __syncthreads();

    const int p = tid >> 4;
    const int i = tid & 15;

    float xr[16];
    {
        const float4* xp = (const float4*)&sX[p * 256 + i * 16];
#pragma unroll
        for (int q = 0; q < 4; q++) *(float4*)&xr[q * 4] = xp[q];
    }

    unsigned long long acc[32];
#pragma unroll
    for (int q = 0; q < 32; q++) acc[q] = 0ull;

#pragma unroll
    for (int j = 0; j < 16; j++) {
        unsigned long long xv = pack2(xr[j], xr[j]);
        const ulonglong2* lp = (const ulonglong2*)&sL[(p * 16 + j) * 64];
#pragma unroll
        for (int q = 0; q < 16; q++) {
            ulonglong2 lv = lp[q];
            ffma2(acc[2 * q],     xv, lv.x);
            ffma2(acc[2 * q + 1], xv, lv.y);
        }
    }

    unsigned short hh[64], ll[64];
#pragma unroll
    for (int q = 0; q < 32; q++) {
        float2 a = unpack2(acc[q]);
        __nv_bfloat16 h0 = __float2bfloat16(a.x);
        __nv_bfloat16 h1 = __float2bfloat16(a.y);
        hh[2 * q]     = __bfloat16_as_ushort(h0);
        hh[2 * q + 1] = __bfloat16_as_ushort(h1);
        ll[2 * q]     = __bfloat16_as_ushort(__float2bfloat16(a.x - __bfloat162float(h0)));
        ll[2 * q + 1] = __bfloat16_as_ushort(__float2bfloat16(a.y - __bfloat162float(h1)));
    }
    size_t off = (size_t)(g0 + p) * 1024 + i * 64;
#pragma unroll
    for (int q = 0; q < 8; q++) {
        *(uint4*)(Thi + off + q * 8) = *(uint4*)&hh[q * 8];
        *(uint4*)(Tlo + off + q * 8) = *(uint4*)&ll[q * 8];
    }
}

// ---------------------------------------------------------------------------
extern "C" void kernel_launch(void* const* d_in, const int* in_sizes, int n_in,
                              void* d_out, int out_size) {
    const float* xyz     = (const float*)d_in[0];
    const float* feat    = (const float*)d_in[1];
    const float* w1      = (const float*)d_in[2];
    const float* b1      = (const float*)d_in[3];
    const float* gamma1  = (const float*)d_in[4];
    const float* beta1   = (const float*)d_in[5];
    const float* mean1   = (const float*)d_in[6];
    const float* var1    = (const float*)d_in[7];
    const float* w2      = (const float*)d_in[8];
    const float* b2      = (const float*)d_in[9];
    const float* wl      = (const float*)d_in[10];
    const float* gamma_l = (const float*)d_in[11];
    const float* beta_l  = (const float*)d_in[12];
    const float* mean_l  = (const float*)d_in[13];
    const float* var_l   = (const float*)d_in[14];
    const float* wf      = (const float*)d_in[15];
    const float* gamma_f = (const float*)d_in[16];
    const float* beta_f  = (const float*)d_in[17];
    const float* mean_f  = (const float*)d_in[18];
    const float* var_f   = (const float*)d_in[19];
    float* out = (float*)d_out;

    float *pd_ptr, *X_ptr, *L0_ptr;
    int *pi_ptr, *idx_ptr;
    unsigned short *hhi, *hlo, *thi, *tlo, *w2hi, *w2lo, *wfhi, *wflo;
    cudaGetSymbolAddress((void**)&pd_ptr, g_pd);
    cudaGetSymbolAddress((void**)&pi_ptr, g_pi);
    cudaGetSymbolAddress((void**)&idx_ptr, g_idx);
    cudaGetSymbolAddress((void**)&hhi, g_h_hi);
    cudaGetSymbolAddress((void**)&hlo, g_h_lo);
    cudaGetSymbolAddress((void**)&X_ptr, g_X);
    cudaGetSymbolAddress((void**)&L0_ptr, g_L0);
    cudaGetSymbolAddress((void**)&thi, g_t_hi);
    cudaGetSymbolAddress((void**)&tlo, g_t_lo);
    cudaGetSymbolAddress((void**)&w2hi, g_w2t_hi);
    cudaGetSymbolAddress((void**)&w2lo, g_w2t_lo);
    cudaGetSymbolAddress((void**)&wfhi, g_wft_hi);
    cudaGetSymbolAddress((void**)&wflo, g_wft_lo);

    knn_part<<<(NPTS / 256) * SPLIT, 256>>>(xyz, pd_ptr, pi_ptr);
    prep_bT<<<(512 * 256 + 255) / 256, 256>>>(w2, w2hi, w2lo, 512, 256);
    prep_bT<<<(1024 * 128 + 255) / 256, 256>>>(wf, wfhi, wflo, 1024, 128);

    // L0 needs no idx — run while KNN results are still in flight order-wise
    cudaFuncSetAttribute(lift0_kernel,
                         cudaFuncAttributeMaxDynamicSharedMemorySize, 83456);
    lift0_kernel<<<NPTS / 256, 256, 83456>>>(
        feat, xyz, wl, gamma_l, beta_l, mean_l, var_l, L0_ptr);

    knn_merge<<<NPTS / 128, 256>>>(pd_ptr, pi_ptr, idx_ptr);

    h_kernel<<<NPTS / 16, 256>>>(xyz, idx_ptr, w1, b1, gamma1, beta1,
                                 mean1, var1, hhi, hlo);

    mma_gemm<128, 256, 512, 0><<<dim3(NPTS / 128, 2), 256>>>(
        hhi, hlo, w2hi, w2lo, b2, nullptr, nullptr, nullptr, xyz, X_ptr);

    cudaFuncSetAttribute(xform_gather,
                         cudaFuncAttributeMaxDynamicSharedMemorySize, 83968);
    xform_gather<<<NPTS / 16, 256, 83968>>>(idx_ptr, L0_ptr, X_ptr, thi, tlo);

    mma_gemm<64, 128, 1024, 1><<<dim3(NPTS / 64, 1), 256>>>(
        thi, tlo, wfhi, wflo, gamma_f, beta_f, mean_f, var_f, xyz, out);
}

// round 16
// speedup vs baseline: 1.2110x; 1.0352x over previous
#include <cuda_runtime.h>
#include <cuda_bf16.h>
#include <cstdint>
#include <float.h>

#define BB    8
#define NN    2048
#define KK    16
#define CIN   64
#define COUT  128
#define BN_EPS 1e-3f
#define LARGE_DIST 1e9f
#define MARGIN 2e-4f

#define SPLIT 4
#define CAND  (NN / SPLIT)   // 512
#define NPTS  (BB * NN)      // 16384

// ---- global scratch -------------------------------------------------------
__device__ float          g_pd[NPTS * SPLIT * KK];
__device__ int            g_pi[NPTS * SPLIT * KK];
__device__ int            g_idx[NPTS * KK];
__device__ unsigned short g_h_hi[(size_t)NPTS * 512];
__device__ unsigned short g_h_lo[(size_t)NPTS * 512];
__device__ float          g_X[(size_t)NPTS * 256];
__device__ float          g_L0[(size_t)NPTS * 64];
__device__ unsigned short g_t_hi[(size_t)NPTS * 1024];
__device__ unsigned short g_t_lo[(size_t)NPTS * 1024];
__device__ unsigned short g_w2t_hi[256 * 512];
__device__ unsigned short g_w2t_lo[256 * 512];
__device__ unsigned short g_wft_hi[128 * 1024];
__device__ unsigned short g_wft_lo[128 * 1024];

// ---- packed fp32x2 helpers ------------------------------------------------
__device__ __forceinline__ unsigned long long pack2(float lo, float hi) {
    unsigned long long r;
    asm("mov.b64 %0, {%1, %2};" : "=l"(r) : "f"(lo), "f"(hi));
    return r;
}
__device__ __forceinline__ float2 unpack2(unsigned long long v) {
    float2 r;
    asm("mov.b64 {%0, %1}, %2;" : "=f"(r.x), "=f"(r.y) : "l"(v));
    return r;
}
__device__ __forceinline__ void ffma2(unsigned long long& a,
                                      unsigned long long x,
                                      unsigned long long y) {
    asm("fma.rn.f32x2 %0, %1, %2, %0;" : "+l"(a) : "l"(x), "l"(y));
}

// ---- mma.sync / async helpers ----------------------------------------------
__device__ __forceinline__ uint32_t smem_u32(const void* p) {
    uint32_t a;
    asm("{ .reg .u64 t; cvta.to.shared.u64 t, %1; cvt.u32.u64 %0, t; }"
        : "=r"(a) : "l"(p));
    return a;
}
__device__ __forceinline__ void ldm_x4(uint32_t* r, uint32_t addr) {
    asm volatile("ldmatrix.sync.aligned.m8n8.x4.shared.b16 {%0,%1,%2,%3}, [%4];"
                 : "=r"(r[0]), "=r"(r[1]), "=r"(r[2]), "=r"(r[3]) : "r"(addr));
}
__device__ __forceinline__ void ldm_x2(uint32_t* r, uint32_t addr) {
    asm volatile("ldmatrix.sync.aligned.m8n8.x2.shared.b16 {%0,%1}, [%2];"
                 : "=r"(r[0]), "=r"(r[1]) : "r"(addr));
}
__device__ __forceinline__ void mma_bf16(float* d, const uint32_t* a,
                                         const uint32_t* b) {
    asm volatile(
        "mma.sync.aligned.m16n8k16.row.col.f32.bf16.bf16.f32 "
        "{%0,%1,%2,%3}, {%4,%5,%6,%7}, {%8,%9}, {%0,%1,%2,%3};"
        : "+f"(d[0]), "+f"(d[1]), "+f"(d[2]), "+f"(d[3])
        : "r"(a[0]), "r"(a[1]), "r"(a[2]), "r"(a[3]), "r"(b[0]), "r"(b[1]));
}
__device__ __forceinline__ void cp16(uint32_t dst, const void* src) {
    asm volatile("cp.async.cg.shared.global [%0], [%1], 16;"
                 :: "r"(dst), "l"(src));
}
#define CP_COMMIT() asm volatile("cp.async.commit_group;" ::: "memory")
#define CP_WAIT(N)  asm volatile("cp.async.wait_group %0;" :: "n"(N) : "memory")

// ---------------------------------------------------------------------------
// KNN
// ---------------------------------------------------------------------------
__device__ __forceinline__ void insert16(float* bd, int* bi, float d, int j) {
    bd[KK - 1] = d; bi[KK - 1] = j;
#pragma unroll
    for (int t = KK - 1; t > 0; --t) {
        if (bd[t] < bd[t - 1]) {
            float td = bd[t]; bd[t] = bd[t - 1]; bd[t - 1] = td;
            int   ti = bi[t]; bi[t] = bi[t - 1]; bi[t - 1] = ti;
        }
    }
}

__global__ __launch_bounds__(256)
void knn_part(const float* __restrict__ xyz,
              float* __restrict__ pd, int* __restrict__ pi) {
    __shared__ __align__(16) float s_x[NN], s_y[NN], s_z[NN], s_pn[NN], s_pen[NN];
    const int tid = threadIdx.x;
    const int qg  = blockIdx.x >> 2;
    const int sp  = blockIdx.x & 3;
    const int g   = qg * 256 + tid;
    const int b   = g >> 11;
    const int n   = g & (NN - 1);

    for (int j = tid; j < NN; j += 256) {
        const float* p = xyz + ((size_t)b * NN + j) * 3;
        float x = p[0], y = p[1], z = p[2];
        float pen = (x != 0.0f || y != 0.0f || z != 0.0f) ? 0.0f : LARGE_DIST;
        s_x[j] = x; s_y[j] = y; s_z[j] = z;
        s_pen[j] = pen;
        s_pn[j]  = x * x + y * y + z * z + pen;
    }
    __syncthreads();

    const float* qp = xyz + ((size_t)b * NN + n) * 3;
    const float qx = qp[0], qy = qp[1], qz = qp[2];
    const float qnorm = qx * qx + qy * qy + qz * qz;
    const unsigned long long mx2 = pack2(-2.0f * qx, -2.0f * qx);
    const unsigned long long my2 = pack2(-2.0f * qy, -2.0f * qy);
    const unsigned long long mz2 = pack2(-2.0f * qz, -2.0f * qz);

    float bd[KK]; int bi[KK];
#pragma unroll
    for (int t = 0; t < KK; t++) { bd[t] = FLT_MAX; bi[t] = 0; }
    float boundp = FLT_MAX;

    const int j0 = sp * CAND;
#pragma unroll 4
    for (int jj = 0; jj < CAND; jj += 4) {
        const int j = j0 + jj;
        ulonglong2 Xv = *(const ulonglong2*)&s_x[j];
        ulonglong2 Yv = *(const ulonglong2*)&s_y[j];
        ulonglong2 Zv = *(const ulonglong2*)&s_z[j];
        ulonglong2 Nv = *(const ulonglong2*)&s_pn[j];
        unsigned long long d0 = Nv.x, d1 = Nv.y;
        ffma2(d0, mx2, Xv.x); ffma2(d0, my2, Yv.x); ffma2(d0, mz2, Zv.x);
        ffma2(d1, mx2, Xv.y); ffma2(d1, my2, Yv.y); ffma2(d1, mz2, Zv.y);
        float2 a = unpack2(d0), c = unpack2(d1);
        float mn = fminf(fminf(a.x, a.y), fminf(c.x, c.y));
        if (mn < boundp) {
#pragma unroll
            for (int t4 = 0; t4 < 4; t4++) {
                float px = s_x[j + t4], py = s_y[j + t4], pz = s_z[j + t4];
                float dx = qx - px, dy = qy - py, dz = qz - pz;
                float d = dx * dx + dy * dy + dz * dz + s_pen[j + t4];
                if (d < bd[KK - 1]) insert16(bd, bi, d, j + t4);
            }
            boundp = bd[KK - 1] - qnorm + MARGIN;
        }
    }

    float* po = pd + ((size_t)g * SPLIT + sp) * KK;
    int*   io = pi + ((size_t)g * SPLIT + sp) * KK;
#pragma unroll
    for (int t = 0; t < KK; t++) { po[t] = bd[t]; io[t] = bi[t]; }
}

__global__ __launch_bounds__(256)
void knn_merge(const float* __restrict__ pd, const int* __restrict__ pi,
               int* __restrict__ idx_out) {
    __shared__ float sd[128][17];
    __shared__ int   si[128][17];
    const int tid  = threadIdx.x;
    const int q    = tid >> 1;
    const int half = tid & 1;
    const int g    = blockIdx.x * 128 + q;

    float bd[KK]; int bi[KK];
#pragma unroll
    for (int t = 0; t < KK; t++) { bd[t] = FLT_MAX; bi[t] = 0; }

    const float* pp = pd + (size_t)g * SPLIT * KK + half * 32;
    const int*   ii = pi + (size_t)g * SPLIT * KK + half * 32;
#pragma unroll 4
    for (int c = 0; c < 32; c++) {
        float d = pp[c];
        if (d < bd[KK - 1]) insert16(bd, bi, d, ii[c]);
    }

    if (half) {
#pragma unroll
        for (int t = 0; t < KK; t++) { sd[q][t] = bd[t]; si[q][t] = bi[t]; }
    }
    __syncthreads();
    if (!half) {
#pragma unroll
        for (int c = 0; c < KK; c++) {
            float d = sd[q][c];
            if (d < bd[KK - 1]) insert16(bd, bi, d, si[q][c]);
        }
#pragma unroll
        for (int t = 0; t < KK; t++) idx_out[(size_t)g * KK + t] = bi[t];
    }
}

// ---------------------------------------------------------------------------
// k2: h precompute -> bf16 hi/lo
// ---------------------------------------------------------------------------
__global__ __launch_bounds__(256)
void h_kernel(const float* __restrict__ xyz, const int* __restrict__ idx,
              const float* __restrict__ w1, const float* __restrict__ b1,
              const float* __restrict__ gamma1, const float* __restrict__ beta1,
              const float* __restrict__ mean1, const float* __restrict__ var1,
              unsigned short* __restrict__ Hhi, unsigned short* __restrict__ Hlo) {
    __shared__ float sw[96], sb[32], ssc[32], ssh[32];
    const int tid = threadIdx.x;
    if (tid < 96) sw[tid] = w1[tid];
    if (tid < 32) {
        sb[tid] = b1[tid];
        float sc = gamma1[tid] * rsqrtf(var1[tid] + BN_EPS);
        ssc[tid] = sc;
        ssh[tid] = beta1[tid] - mean1[tid] * sc;
    }
    __syncthreads();

    const int g0 = blockIdx.x * 16;
    const int p  = tid >> 4;
    const int k  = tid & 15;
    const int g  = g0 + p;
    const int b  = g >> 11;
    const int n  = g & (NN - 1);
    const int nbr = idx[(size_t)g * KK + k];

    const float* qp = xyz + ((size_t)b * NN + n) * 3;
    const float* np = xyz + ((size_t)b * NN + nbr) * 3;
    float qx = qp[0], qy = qp[1], qz = qp[2];
    float px = np[0], py = np[1], pz = np[2];
    float nm = (px != 0.0f || py != 0.0f || pz != 0.0f) ? 1.0f : 0.0f;
    float r0 = nm * (px - qx), r1 = nm * (py - qy), r2 = nm * (pz - qz);

    unsigned short hh[32], ll[32];
#pragma unroll
    for (int d = 0; d < 32; d++) {
        float v = r0 * sw[d] + r1 * sw[32 + d] + r2 * sw[64 + d] + sb[d];
        v = fmaxf(v, 0.0f);
        v = v * ssc[d] + ssh[d];
        __nv_bfloat16 hv = __float2bfloat16(v);
        float res = v - __bfloat162float(hv);
        hh[d] = __bfloat16_as_ushort(hv);
        ll[d] = __bfloat16_as_ushort(__float2bfloat16(res));
    }
    size_t off = (size_t)g * 512 + k * 32;
#pragma unroll
    for (int q = 0; q < 4; q++) {
        *(uint4*)(Hhi + off + q * 8) = *(uint4*)&hh[q * 8];
        *(uint4*)(Hlo + off + q * 8) = *(uint4*)&ll[q * 8];
    }
}

// ---------------------------------------------------------------------------
// prep: transpose + bf16-split a weight matrix  W[K][N] -> out[N][K]
// ---------------------------------------------------------------------------
__global__ void prep_bT(const float* __restrict__ W,
                        unsigned short* __restrict__ hi,
                        unsigned short* __restrict__ lo, int K, int N) {
    int i = blockIdx.x * 256 + threadIdx.x;
    if (i >= K * N) return;
    int n = i % N, k = i / N;
    float v = W[i];
    __nv_bfloat16 h = __float2bfloat16(v);
    float r = v - __bfloat162float(h);
    hi[(size_t)n * K + k] = __bfloat16_as_ushort(h);
    lo[(size_t)n * K + k] = __bfloat16_as_ushort(__float2bfloat16(r));
}

// ---------------------------------------------------------------------------
// lift0: L0[p] = relu(BN(feat[p] @ wl)) * mask[p]
// ---------------------------------------------------------------------------
__global__ __launch_bounds__(256)
void lift0_kernel(const float* __restrict__ feat, const float* __restrict__ xyz,
                  const float* __restrict__ wl,
                  const float* __restrict__ gamma_l, const float* __restrict__ beta_l,
                  const float* __restrict__ mean_l, const float* __restrict__ var_l,
                  float* __restrict__ L0) {
    extern __shared__ float sm0[];
    float* As    = sm0;
    float* Bs    = sm0 + 16384;
    float* smask = sm0 + 20480;
    float* ssc   = sm0 + 20736;
    float* ssh   = sm0 + 20800;

    const int tid  = threadIdx.x;
    const int row0 = blockIdx.x * 256;

    {
        const float* np = xyz + (size_t)(row0 + tid) * 3;
        smask[tid] = (np[0] != 0.0f || np[1] != 0.0f || np[2] != 0.0f) ? 1.0f : 0.0f;
        if (tid < 64) {
            float sc = gamma_l[tid] * rsqrtf(var_l[tid] + BN_EPS);
            ssc[tid] = sc;
            ssh[tid] = beta_l[tid] - mean_l[tid] * sc;
        }
    }
    {
        int kr = tid >> 4;
        int cc = (tid & 15) * 4;
#pragma unroll
        for (int h2 = 0; h2 < 4; h2++)
            *(float4*)&Bs[(kr + h2 * 16) * 64 + cc] =
                *(const float4*)(wl + (size_t)(kr + h2 * 16) * 64 + cc);
    }
    {
        int cc = (tid & 15) * 4;
#pragma unroll
        for (int h2 = 0; h2 < 16; h2++) {
            int r = (tid >> 4) + h2 * 16;
            float4 f = *(const float4*)(feat + (size_t)(row0 + r) * 64 + cc);
            As[(cc + 0) * 256 + r] = f.x;
            As[(cc + 1) * 256 + r] = f.y;
            As[(cc + 2) * 256 + r] = f.z;
            As[(cc + 3) * 256 + r] = f.w;
        }
    }
    __syncthreads();

    const int tx = tid & 7;
    const int ty = tid >> 3;
    unsigned long long acc[8][4];
#pragma unroll
    for (int i = 0; i < 8; i++)
#pragma unroll
        for (int q = 0; q < 4; q++) acc[i][q] = 0ull;

#pragma unroll 8
    for (int kk = 0; kk < 64; kk++) {
        float a[8];
        *(float4*)&a[0] = *(const float4*)&As[kk * 256 + ty * 8];
        *(float4*)&a[4] = *(const float4*)&As[kk * 256 + ty * 8 + 4];
        ulonglong2 bA = *(const ulonglong2*)&Bs[kk * 64 + tx * 8];
        ulonglong2 bB = *(const ulonglong2*)&Bs[kk * 64 + tx * 8 + 4];
#pragma unroll
        for (int i = 0; i < 8; i++) {
            unsigned long long a2 = pack2(a[i], a[i]);
            ffma2(acc[i][0], a2, bA.x);
            ffma2(acc[i][1], a2, bA.y);
            ffma2(acc[i][2], a2, bB.x);
            ffma2(acc[i][3], a2, bB.y);
        }
    }

#pragma unroll
    for (int i = 0; i < 8; i++) {
        int rloc = ty * 8 + i;
        float m  = smask[rloc];
        float v[8];
#pragma unroll
        for (int q = 0; q < 8; q++) {
            float2 p = unpack2(acc[i][q >> 1]);
            int nc = tx * 8 + q;
            float x = ((q & 1) ? p.y : p.x) * ssc[nc] + ssh[nc];
            v[q] = fmaxf(x, 0.0f) * m;
        }
        float* cp = L0 + (size_t)(row0 + rloc) * 64 + tx * 8;
        *(float4*)cp       = make_float4(v[0], v[1], v[2], v[3]);
        *(float4*)(cp + 4) = make_float4(v[4], v[5], v[6], v[7]);
    }
}

// ---------------------------------------------------------------------------
// mma.sync bf16 3-term GEMM, cp.async DOUBLE-BUFFERED (dynamic smem, 2 stages)
// ---------------------------------------------------------------------------
template<int BM, int NMAT, int KTOT, int EPI>
__global__ __launch_bounds__(256)
void mma_gemm(const unsigned short* __restrict__ Ahi,
              const unsigned short* __restrict__ Alo,
              const unsigned short* __restrict__ Bhi,
              const unsigned short* __restrict__ Blo,
              const float* __restrict__ e0, const float* __restrict__ e1,
              const float* __restrict__ e2, const float* __restrict__ e3,
              const float* __restrict__ xyz, float* __restrict__ C) {
    constexpr int MT    = BM / 32;
    constexpr int LDS_H = 40;
    constexpr int ASZ   = BM * LDS_H;     // elems
    constexpr int BSZ   = 128 * LDS_H;    // elems
    constexpr int STAGE = 2 * ASZ + 2 * BSZ;   // elems per stage
    constexpr int NT    = KTOT / 32;

    extern __shared__ __align__(16) unsigned short dsm[];

    const int tid  = threadIdx.x;
    const int lane = tid & 31;
    const int wid  = tid >> 5;
    const int wr   = wid >> 2;
    const int wc   = wid & 3;
    const int g0   = blockIdx.x * BM;
    const int col0 = blockIdx.y * 128;

    const uint32_t base = smem_u32(dsm);
    // byte offsets inside a stage
    const uint32_t offAl = ASZ * 2;
    const uint32_t offBh = 2 * ASZ * 2;
    const uint32_t offBl = (2 * ASZ + BSZ) * 2;
    const uint32_t stageB = STAGE * 2;

    // per-thread load coords
    const int arow = tid >> 2;           // with BM*4/256 passes
    const int ac8  = (tid & 3) * 8;
    const int brow = tid >> 2;
    const int bc8  = (tid & 3) * 8;

    auto load_tile = [&](int t, int s) {
        const int k0 = t * 32;
        const uint32_t sb = base + s * stageB;
#pragma unroll
        for (int h = 0; h < BM / 64; h++) {
            int row = arow + h * 64;
            uint32_t d = sb + (uint32_t)(row * LDS_H + ac8) * 2;
            size_t src = (size_t)(g0 + row) * KTOT + k0 + ac8;
            cp16(d, Ahi + src);
            cp16(d + offAl, Alo + src);
        }
#pragma unroll
        for (int h = 0; h < 2; h++) {
            int row = brow + h * 64;
            uint32_t d = sb + offBh + (uint32_t)(row * LDS_H + bc8) * 2;
            size_t src = (size_t)(col0 + row) * KTOT + k0 + bc8;
            cp16(d, Bhi + src);
            cp16(d + (offBl - offBh), Blo + src);
        }
        CP_COMMIT();
    };

    float acc[MT][4][4];
#pragma unroll
    for (int m = 0; m < MT; m++)
#pragma unroll
        for (int n = 0; n < 4; n++)
#pragma unroll
            for (int q = 0; q < 4; q++) acc[m][n][q] = 0.0f;

    const int q8 = lane >> 3;
    const int r8 = lane & 7;

    load_tile(0, 0);

    for (int t = 0; t < NT; t++) {
        const int cur = t & 1;
        if (t + 1 < NT) {
            load_tile(t + 1, cur ^ 1);
            CP_WAIT(1);
        } else {
            CP_WAIT(0);
        }
        __syncthreads();

        const uint32_t sb   = base + cur * stageB;
        const uint32_t aHiB = sb,          aLoB = sb + offAl;
        const uint32_t bHiB = sb + offBh,  bLoB = sb + offBl;

#pragma unroll
        for (int ks = 0; ks < 2; ks++) {
            const int kk = ks * 16;
            uint32_t ah[MT][4], al[MT][4];
#pragma unroll
            for (int m = 0; m < MT; m++) {
                int ar = wr * (BM / 2) + m * 16 + (q8 & 1) * 8 + r8;
                int acl = kk + (q8 >> 1) * 8;
                uint32_t off = (uint32_t)(ar * LDS_H + acl) * 2;
                ldm_x4(ah[m], aHiB + off);
                ldm_x4(al[m], aLoB + off);
            }
            uint32_t bh[4][2], bl[4][2];
#pragma unroll
            for (int n = 0; n < 4; n++) {
                int nr = wc * 32 + n * 8 + r8;
                int ncl = kk + (q8 & 1) * 8;
                uint32_t off = (uint32_t)(nr * LDS_H + ncl) * 2;
                ldm_x2(bh[n], bHiB + off);
                ldm_x2(bl[n], bLoB + off);
            }
#pragma unroll
            for (int m = 0; m < MT; m++)
#pragma unroll
                for (int n = 0; n < 4; n++) {
                    mma_bf16(acc[m][n], ah[m], bh[n]);
                    mma_bf16(acc[m][n], ah[m], bl[n]);
                    mma_bf16(acc[m][n], al[m], bh[n]);
                }
        }
        __syncthreads();
    }

#pragma unroll
    for (int m = 0; m < MT; m++) {
        int r1 = g0 + wr * (BM / 2) + m * 16 + (lane >> 2);
        int r2 = r1 + 8;
        float m1 = 1.0f, m2 = 1.0f;
        if (EPI == 1) {
            const float* p1 = xyz + (size_t)r1 * 3;
            const float* p2 = xyz + (size_t)r2 * 3;
            m1 = (p1[0] != 0.0f || p1[1] != 0.0f || p1[2] != 0.0f) ? 1.0f : 0.0f;
            m2 = (p2[0] != 0.0f || p2[1] != 0.0f || p2[2] != 0.0f) ? 1.0f : 0.0f;
        }
#pragma unroll
        for (int n = 0; n < 4; n++) {
            int c = col0 + wc * 32 + n * 8 + (lane & 3) * 2;
            float v0 = acc[m][n][0], v1 = acc[m][n][1];
            float v2 = acc[m][n][2], v3 = acc[m][n][3];
            if (EPI == 0) {
                float bb0 = e0[c], bb1 = e0[c + 1];
                v0 += bb0; v1 += bb1; v2 += bb0; v3 += bb1;
            } else {
                float sc0 = e0[c] * rsqrtf(e3[c] + BN_EPS);
                float sh0 = e1[c] - e2[c] * sc0;
                float sc1 = e0[c + 1] * rsqrtf(e3[c + 1] + BN_EPS);
                float sh1 = e1[c + 1] - e2[c + 1] * sc1;
                v0 = fmaxf(v0 * sc0 + sh0, 0.0f) * m1;
                v1 = fmaxf(v1 * sc1 + sh1, 0.0f) * m1;
                v2 = fmaxf(v2 * sc0 + sh0, 0.0f) * m2;
                v3 = fmaxf(v3 * sc1 + sh1, 0.0f) * m2;
            }
            *(float2*)(C + (size_t)r1 * NMAT + c) = make_float2(v0, v1);
            *(float2*)(C + (size_t)r2 * NMAT + c) = make_float2(v2, v3);
        }
    }
}

// ---------------------------------------------------------------------------
// xform_gather: gather L0 rows + transformed = X @ lifted -> bf16 hi/lo.
// ---------------------------------------------------------------------------
__global__ __launch_bounds__(256)
void xform_gather(const int* __restrict__ idx, const float* __restrict__ L0,
                  const float* __restrict__ Xg,
                  unsigned short* __restrict__ Thi,
                  unsigned short* __restrict__ Tlo) {
    extern __shared__ float sm[];
    float* sL   = sm;
    float* sX   = sm + 16384;
    int*   sidx = (int*)(sm + 20480);

    const int tid  = threadIdx.x;
    const int g0   = blockIdx.x * 16;
    const int row0 = blockIdx.x * 256;
    const int bbase = (g0 >> 11) << 11;

    sidx[tid] = idx[row0 + tid];
    for (int e = tid * 4; e < 4096; e += 1024)
        *(float4*)&sX[e] = *(const float4*)(Xg + (size_t)g0 * 256 + e);
    __syncthreads();

    {
        const int rsub = tid >> 2;
        const int c0   = (tid & 3) * 4;
#pragma unroll
        for (int rc = 0; rc < 4; rc++) {
            int rloc = rc * 64 + rsub;
            size_t lrow = (size_t)(bbase + sidx[rloc]) * 64;
#pragma unroll
            for (int cc = 0; cc < 4; cc++) {
                int c = c0 + cc * 16;
                *(float4*)&sL[rloc * 64 + c] = *(const float4*)(L0 + lrow + c);
            }
        }
    }
    __syncthreads();

    const int p = tid >> 4;
    const int i = tid & 15;

    float xr[16];
    {
        const float4* xp = (const float4*)&sX[p * 256 + i * 16];
#pragma unroll
        for (int q = 0; q < 4; q++) *(float4*)&xr[q * 4] = xp[q];
    }

    unsigned long long acc[32];
#pragma unroll
    for (int q = 0; q < 32; q++) acc[q] = 0ull;

#pragma unroll
    for (int j = 0; j < 16; j++) {
        unsigned long long xv = pack2(xr[j], xr[j]);
        const ulonglong2* lp = (const ulonglong2*)&sL[(p * 16 + j) * 64];
#pragma unroll
        for (int q = 0; q < 16; q++) {
            ulonglong2 lv = lp[q];
            ffma2(acc[2 * q],     xv, lv.x);
            ffma2(acc[2 * q + 1], xv, lv.y);
        }
    }

    unsigned short hh[64], ll[64];
#pragma unroll
    for (int q = 0; q < 32; q++) {
        float2 a = unpack2(acc[q]);
        __nv_bfloat16 h0 = __float2bfloat16(a.x);
        __nv_bfloat16 h1 = __float2bfloat16(a.y);
        hh[2 * q]     = __bfloat16_as_ushort(h0);
        hh[2 * q + 1] = __bfloat16_as_ushort(h1);
        ll[2 * q]     = __bfloat16_as_ushort(__float2bfloat16(a.x - __bfloat162float(h0)));
        ll[2 * q + 1] = __bfloat16_as_ushort(__float2bfloat16(a.y - __bfloat162float(h1)));
    }
    size_t off = (size_t)(g0 + p) * 1024 + i * 64;
#pragma unroll
    for (int q = 0; q < 8; q++) {
        *(uint4*)(Thi + off + q * 8) = *(uint4*)&hh[q * 8];
        *(uint4*)(Tlo + off + q * 8) = *(uint4*)&ll[q * 8];
    }
}

// ---------------------------------------------------------------------------
extern "C" void kernel_launch(void* const* d_in, const int* in_sizes, int n_in,
                              void* d_out, int out_size) {
    const float* xyz     = (const float*)d_in[0];
    const float* feat    = (const float*)d_in[1];
    const float* w1      = (const float*)d_in[2];
    const float* b1      = (const float*)d_in[3];
    const float* gamma1  = (const float*)d_in[4];
    const float* beta1   = (const float*)d_in[5];
    const float* mean1   = (const float*)d_in[6];
    const float* var1    = (const float*)d_in[7];
    const float* w2      = (const float*)d_in[8];
    const float* b2      = (const float*)d_in[9];
    const float* wl      = (const float*)d_in[10];
    const float* gamma_l = (const float*)d_in[11];
    const float* beta_l  = (const float*)d_in[12];
    const float* mean_l  = (const float*)d_in[13];
    const float* var_l   = (const float*)d_in[14];
    const float* wf      = (const float*)d_in[15];
    const float* gamma_f = (const float*)d_in[16];
    const float* beta_f  = (const float*)d_in[17];
    const float* mean_f  = (const float*)d_in[18];
    const float* var_f   = (const float*)d_in[19];
    float* out = (float*)d_out;

    float *pd_ptr, *X_ptr, *L0_ptr;
    int *pi_ptr, *idx_ptr;
    unsigned short *hhi, *hlo, *thi, *tlo, *w2hi, *w2lo, *wfhi, *wflo;
    cudaGetSymbolAddress((void**)&pd_ptr, g_pd);
    cudaGetSymbolAddress((void**)&pi_ptr, g_pi);
    cudaGetSymbolAddress((void**)&idx_ptr, g_idx);
    cudaGetSymbolAddress((void**)&hhi, g_h_hi);
    cudaGetSymbolAddress((void**)&hlo, g_h_lo);
    cudaGetSymbolAddress((void**)&X_ptr, g_X);
    cudaGetSymbolAddress((void**)&L0_ptr, g_L0);
    cudaGetSymbolAddress((void**)&thi, g_t_hi);
    cudaGetSymbolAddress((void**)&tlo, g_t_lo);
    cudaGetSymbolAddress((void**)&w2hi, g_w2t_hi);
    cudaGetSymbolAddress((void**)&w2lo, g_w2t_lo);
    cudaGetSymbolAddress((void**)&wfhi, g_wft_hi);
    cudaGetSymbolAddress((void**)&wflo, g_wft_lo);

    // order chosen so knn_part is the 4th launch (profiler capture slot)
    prep_bT<<<(512 * 256 + 255) / 256, 256>>>(w2, w2hi, w2lo, 512, 256);
    prep_bT<<<(1024 * 128 + 255) / 256, 256>>>(wf, wfhi, wflo, 1024, 128);

    cudaFuncSetAttribute(lift0_kernel,
                         cudaFuncAttributeMaxDynamicSharedMemorySize, 83456);
    lift0_kernel<<<NPTS / 256, 256, 83456>>>(
        feat, xyz, wl, gamma_l, beta_l, mean_l, var_l, L0_ptr);

    knn_part<<<(NPTS / 256) * SPLIT, 256>>>(xyz, pd_ptr, pi_ptr);
    knn_merge<<<NPTS / 128, 256>>>(pd_ptr, pi_ptr, idx_ptr);

    h_kernel<<<NPTS / 16, 256>>>(xyz, idx_ptr, w1, b1, gamma1, beta1,
                                 mean1, var1, hhi, hlo);

    // k3: 2-stage cp.async, dyn smem 81920 B
    cudaFuncSetAttribute(mma_gemm<128, 256, 512, 0>,
                         cudaFuncAttributeMaxDynamicSharedMemorySize, 81920);
    mma_gemm<128, 256, 512, 0><<<dim3(NPTS / 128, 2), 256, 81920>>>(
        hhi, hlo, w2hi, w2lo, b2, nullptr, nullptr, nullptr, xyz, X_ptr);

    cudaFuncSetAttribute(xform_gather,
                         cudaFuncAttributeMaxDynamicSharedMemorySize, 83968);
    xform_gather<<<NPTS / 16, 256, 83968>>>(idx_ptr, L0_ptr, X_ptr, thi, tlo);

    // k6: 2-stage cp.async, dyn smem 61440 B
    cudaFuncSetAttribute(mma_gemm<64, 128, 1024, 1>,
                         cudaFuncAttributeMaxDynamicSharedMemorySize, 61440);
    mma_gemm<64, 128, 1024, 1><<<dim3(NPTS / 64, 1), 256, 61440>>>(
        thi, tlo, wfhi, wflo, gamma_f, beta_f, mean_f, var_f, xyz, out);
}